// round 3
// baseline (speedup 1.0000x reference)
#include <cuda_runtime.h>

// ============================================================================
// EGNN layer, fp32, fused edge-tile GEMMs + node MLPs.
// Outputs (concatenated in d_out): h_out [N,128], x_out [N,3], v_out [N,3]
// ============================================================================

#define NTHREADS 256
#define TE 64           // edges (or nodes) per block
#define MAXN 65536

// Scratch (allocation-free rule: __device__ globals)
__device__ float g_mi[(size_t)MAXN * 128];  // segment_sum of e_ij*m_ij
__device__ float g_aggx[(size_t)MAXN * 3];  // segment_sum of x_update
__device__ int   g_hase[MAXN];              // has outgoing edge flag

__device__ __forceinline__ float siluf(float v) { return v / (1.0f + __expf(-v)); }
__device__ __forceinline__ float sigmf(float v) { return 1.0f / (1.0f + __expf(-v)); }

// Copy n4 float4s of weights gmem -> smem (contiguous)
__device__ __forceinline__ void load_w(float* s_w, const float* __restrict__ W,
                                       int n4, int tid) {
    const float4* src = (const float4*)W;
    float4* dst = (float4*)s_w;
    for (int i = tid; i < n4; i += NTHREADS) dst[i] = src[i];
}

// Accumulate one K=32 chunk: A tile [64 x strideA] (rows=edges), W chunk [32 x 128].
// Thread tile: 4 edges (ty*4..) x 8 outs (tx*8..).
__device__ __forceinline__ void mma128(float (&acc)[4][8], const float* sA, int strideA,
                                       int kbase, const float* s_w, int tx, int ty) {
#pragma unroll
    for (int kk = 0; kk < 32; kk += 4) {
        float a_[4][4];
#pragma unroll
        for (int i = 0; i < 4; i++) {
            float4 v = *(const float4*)(sA + (ty * 4 + i) * strideA + kbase + kk);
            a_[i][0] = v.x; a_[i][1] = v.y; a_[i][2] = v.z; a_[i][3] = v.w;
        }
#pragma unroll
        for (int t = 0; t < 4; t++) {
            float4 b0 = *(const float4*)(s_w + (kk + t) * 128 + tx * 8);
            float4 b1 = *(const float4*)(s_w + (kk + t) * 128 + tx * 8 + 4);
#pragma unroll
            for (int i = 0; i < 4; i++) {
                float av = a_[i][t];
                acc[i][0] += av * b0.x; acc[i][1] += av * b0.y;
                acc[i][2] += av * b0.z; acc[i][3] += av * b0.w;
                acc[i][4] += av * b1.x; acc[i][5] += av * b1.y;
                acc[i][6] += av * b1.z; acc[i][7] += av * b1.w;
            }
        }
    }
}

// Same but output width 64: thread tile 4 edges x 4 outs (tx*4..)
__device__ __forceinline__ void mma64(float (&acc)[4][4], const float* sA, int strideA,
                                      int kbase, const float* s_w, int tx, int ty) {
#pragma unroll
    for (int kk = 0; kk < 32; kk += 4) {
        float a_[4][4];
#pragma unroll
        for (int i = 0; i < 4; i++) {
            float4 v = *(const float4*)(sA + (ty * 4 + i) * strideA + kbase + kk);
            a_[i][0] = v.x; a_[i][1] = v.y; a_[i][2] = v.z; a_[i][3] = v.w;
        }
#pragma unroll
        for (int t = 0; t < 4; t++) {
            float4 b0 = *(const float4*)(s_w + (kk + t) * 64 + tx * 4);
#pragma unroll
            for (int i = 0; i < 4; i++) {
                float av = a_[i][t];
                acc[i][0] += av * b0.x; acc[i][1] += av * b0.y;
                acc[i][2] += av * b0.z; acc[i][3] += av * b0.w;
            }
        }
    }
}

// ============================================================================
// Edge kernel: all four edge-side GEMMs fused per 64-edge tile.
// ============================================================================
// smem layout (floats):
//   s_ef  [64*260]    gathered h[row]||h[col]  (stride 260, cols 0..255 valid)
//   s_t   [64*132]    t1 = silu(ef@W1+...)
//   s_m   [64*132]    m_ij = silu(t1@W2+b2)
//   s_w   [4096]      streamed weight chunk (32x128)
//   consts + per-edge meta
#define E_SMEM_FLOATS 39168

__global__ __launch_bounds__(NTHREADS, 1)
void egnn_edge_kernel(const float* __restrict__ h, const float* __restrict__ x,
                      const float* __restrict__ eattr, const int* __restrict__ ei,
                      const float* __restrict__ eW1, const float* __restrict__ eb1,
                      const float* __restrict__ eW2, const float* __restrict__ eb2,
                      const float* __restrict__ cW1, const float* __restrict__ cb1,
                      const float* __restrict__ cW2,
                      const float* __restrict__ iW1, const float* __restrict__ ib1,
                      const float* __restrict__ iW2, const float* __restrict__ ib2,
                      float* __restrict__ mi, float* __restrict__ aggx,
                      int* __restrict__ hase, int E) {
    extern __shared__ float sm[];
    float* s_ef   = sm;                 // 16640
    float* s_t    = s_ef + 16640;       // 8448
    float* s_m    = s_t + 8448;         // 8448
    float* s_w    = s_m + 8448;         // 4096
    float* s_b1   = s_w + 4096;         // 128
    float* s_b2   = s_b1 + 128;         // 128
    float* s_cb1  = s_b2 + 128;         // 128
    float* s_cW2  = s_cb1 + 128;        // 128
    float* s_ib1  = s_cW2 + 128;        // 64
    float* s_iW2  = s_ib1 + 64;         // 64
    float* s_w256 = s_iW2 + 64;         // 128
    float* s_w257 = s_w256 + 128;       // 128
    float* s_ds   = s_w257 + 128;       // 64
    float* s_ea   = s_ds + 64;          // 64
    float* s_xd   = s_ea + 64;          // 192
    float* s_red  = s_xd + 192;         // 64
    float* s_phi  = s_red + 64;         // 64
    float* s_eij  = s_phi + 64;         // 64
    int*   s_row  = (int*)(s_eij + 64); // 64
    int*   s_col  = s_row + 64;         // 64

    const int tid = threadIdx.x;
    const int tx = tid & 15;
    const int ty = tid >> 4;
    const int e0 = blockIdx.x * TE;
    const int ne = min(TE, E - e0);

    // Stage constants
    if (tid < 128) {
        s_b1[tid]   = eb1[tid];
        s_b2[tid]   = eb2[tid];
        s_cb1[tid]  = cb1[tid];
        s_cW2[tid]  = cW2[tid];
        s_w256[tid] = eW1[256 * 128 + tid];
        s_w257[tid] = eW1[257 * 128 + tid];
    } else {
        int t = tid - 128;
        if (t < 64) { s_ib1[t] = ib1[t]; s_iW2[t] = iW2[t]; }
    }
    // Stage per-edge meta
    if (tid < TE) {
        int r = 0, c = 0;
        float dsv = 0.f, eav = 0.f, dx = 0.f, dy = 0.f, dz = 0.f;
        if (tid < ne) {
            int e = e0 + tid;
            r = ei[e];
            c = ei[E + e];
            dx = x[r * 3 + 0] - x[c * 3 + 0];
            dy = x[r * 3 + 1] - x[c * 3 + 1];
            dz = x[r * 3 + 2] - x[c * 3 + 2];
            dsv = dx * dx + dy * dy + dz * dz;
            eav = eattr[e];
        }
        s_row[tid] = r; s_col[tid] = c; s_ds[tid] = dsv; s_ea[tid] = eav;
        s_xd[tid * 3 + 0] = dx; s_xd[tid * 3 + 1] = dy; s_xd[tid * 3 + 2] = dz;
    }
    __syncthreads();

    // Gather h[row]||h[col] into s_ef (float4 granules)
    for (int idx = tid; idx < TE * 64; idx += NTHREADS) {
        int e = idx >> 6;
        int k4 = idx & 63;
        const float4* src = (k4 < 32)
            ? ((const float4*)(h + (size_t)s_row[e] * 128) + k4)
            : ((const float4*)(h + (size_t)s_col[e] * 128) + (k4 - 32));
        *(float4*)(s_ef + e * 260 + k4 * 4) = *src;
    }

    float acc[4][8];

    // ---- GEMM1: t1 = silu(ef @ eW1[0:256] + ds*w256 + ea*w257 + b1) ----
#pragma unroll
    for (int i = 0; i < 4; i++)
#pragma unroll
        for (int j = 0; j < 8; j++) acc[i][j] = 0.f;
    for (int kc = 0; kc < 256; kc += 32) {
        __syncthreads();
        load_w(s_w, eW1 + kc * 128, 1024, tid);
        __syncthreads();
        mma128(acc, s_ef, 260, kc, s_w, tx, ty);
    }
#pragma unroll
    for (int i = 0; i < 4; i++) {
        int e = ty * 4 + i;
        float ds = s_ds[e], ea = s_ea[e];
#pragma unroll
        for (int j = 0; j < 8; j++) {
            int o = tx * 8 + j;
            float v = acc[i][j] + ds * s_w256[o] + ea * s_w257[o] + s_b1[o];
            s_t[e * 132 + o] = siluf(v);
        }
    }

    // ---- GEMM2: m = silu(t1 @ eW2 + b2) ----
#pragma unroll
    for (int i = 0; i < 4; i++)
#pragma unroll
        for (int j = 0; j < 8; j++) acc[i][j] = 0.f;
    for (int kc = 0; kc < 128; kc += 32) {
        __syncthreads();
        load_w(s_w, eW2 + kc * 128, 1024, tid);
        __syncthreads();
        mma128(acc, s_t, 132, kc, s_w, tx, ty);
    }
#pragma unroll
    for (int i = 0; i < 4; i++) {
        int e = ty * 4 + i;
#pragma unroll
        for (int j = 0; j < 8; j++) {
            int o = tx * 8 + j;
            s_m[e * 132 + o] = siluf(acc[i][j] + s_b2[o]);
        }
    }

    // ---- GEMM3 (inf head, width 64) fused with dot(inf_W2) ----
    float acc2[4][4];
#pragma unroll
    for (int i = 0; i < 4; i++)
#pragma unroll
        for (int j = 0; j < 4; j++) acc2[i][j] = 0.f;
    for (int kc = 0; kc < 128; kc += 32) {
        __syncthreads();
        load_w(s_w, iW1 + kc * 64, 512, tid);
        __syncthreads();
        mma64(acc2, s_m, 132, kc, s_w, tx, ty);
    }
#pragma unroll
    for (int i = 0; i < 4; i++) {
        float p = 0.f;
#pragma unroll
        for (int j = 0; j < 4; j++) {
            int o = tx * 4 + j;
            p += siluf(acc2[i][j] + s_ib1[o]) * s_iW2[o];
        }
#pragma unroll
        for (int off = 8; off >= 1; off >>= 1)
            p += __shfl_xor_sync(0xffffffffu, p, off);
        if (tx == 0) s_red[ty * 4 + i] = p;
    }

    // ---- GEMM4 (coord head, width 128) fused with dot(coord_W2) ----
#pragma unroll
    for (int i = 0; i < 4; i++)
#pragma unroll
        for (int j = 0; j < 8; j++) acc[i][j] = 0.f;
    for (int kc = 0; kc < 128; kc += 32) {
        __syncthreads();
        load_w(s_w, cW1 + kc * 128, 1024, tid);
        __syncthreads();
        mma128(acc, s_m, 132, kc, s_w, tx, ty);
    }
#pragma unroll
    for (int i = 0; i < 4; i++) {
        float p = 0.f;
#pragma unroll
        for (int j = 0; j < 8; j++) {
            int o = tx * 8 + j;
            p += siluf(acc[i][j] + s_cb1[o]) * s_cW2[o];
        }
#pragma unroll
        for (int off = 8; off >= 1; off >>= 1)
            p += __shfl_xor_sync(0xffffffffu, p, off);
        if (tx == 0) s_phi[ty * 4 + i] = p;
    }
    __syncthreads();

    // ---- per-edge epilogue: e_ij, x_update scatter ----
    if (tid < TE) {
        float ev = sigmf(s_red[tid] + ib2[0]);
        s_eij[tid] = ev;
        if (tid < ne) {
            int r = s_row[tid];
            float f = ev * s_phi[tid];
            atomicAdd(&aggx[(size_t)r * 3 + 0], f * s_xd[tid * 3 + 0]);
            atomicAdd(&aggx[(size_t)r * 3 + 1], f * s_xd[tid * 3 + 1]);
            atomicAdd(&aggx[(size_t)r * 3 + 2], f * s_xd[tid * 3 + 2]);
            hase[r] = 1;
        }
    }
    __syncthreads();

    // ---- m_i scatter: m_i[row] += e_ij * m_ij ----
    for (int idx = tid; idx < TE * 128; idx += NTHREADS) {
        int e = idx >> 7;
        int j = idx & 127;
        if (e < ne)
            atomicAdd(&mi[(size_t)s_row[e] * 128 + j], s_eij[e] * s_m[e * 132 + j]);
    }
}

// ============================================================================
// Node kernel: vel MLP, node MLP, x_out / v_out / h_out
// ============================================================================
#define N_SMEM_FLOATS 29760

__global__ __launch_bounds__(NTHREADS, 1)
void egnn_node_kernel(const float* __restrict__ h, const float* __restrict__ x,
                      const float* __restrict__ vinit,
                      const float* __restrict__ nW1, const float* __restrict__ nb1,
                      const float* __restrict__ nW2, const float* __restrict__ nb2,
                      const float* __restrict__ vW1, const float* __restrict__ vb1,
                      const float* __restrict__ vW2,
                      const float* __restrict__ mi, const float* __restrict__ aggx,
                      const int* __restrict__ hase,
                      float* __restrict__ out, int N, float invNm1) {
    extern __shared__ float sm[];
    float* s_in  = sm;                // 16640 : [h | m_i], stride 260
    float* s_t   = s_in + 16640;      // 8448
    float* s_w   = s_t + 8448;        // 4096
    float* s_nb1 = s_w + 4096;        // 128
    float* s_nb2 = s_nb1 + 128;       // 128
    float* s_vb1 = s_nb2 + 128;       // 128
    float* s_vW2 = s_vb1 + 128;       // 128
    float* s_vel = s_vW2 + 128;       // 64

    const int tid = threadIdx.x;
    const int tx = tid & 15;
    const int ty = tid >> 4;
    const int n0 = blockIdx.x * TE;
    const int nn = min(TE, N - n0);

    if (tid < 128) {
        s_nb1[tid] = nb1[tid];
        s_nb2[tid] = nb2[tid];
        s_vb1[tid] = vb1[tid];
        s_vW2[tid] = vW2[tid];
    }

    // Stage [h | m_i]
    for (int idx = tid; idx < TE * 64; idx += NTHREADS) {
        int e = idx >> 6;
        int k4 = idx & 63;
        float4 v = make_float4(0.f, 0.f, 0.f, 0.f);
        if (e < nn) {
            size_t n = (size_t)(n0 + e);
            v = (k4 < 32) ? ((const float4*)(h + n * 128))[k4]
                          : ((const float4*)(mi + n * 128))[k4 - 32];
        }
        *(float4*)(s_in + e * 260 + k4 * 4) = v;
    }

    float acc[4][8];

    // ---- vel: scale = silu(h @ vW1 + vb1) . vW2 ----
#pragma unroll
    for (int i = 0; i < 4; i++)
#pragma unroll
        for (int j = 0; j < 8; j++) acc[i][j] = 0.f;
    for (int kc = 0; kc < 128; kc += 32) {
        __syncthreads();
        load_w(s_w, vW1 + kc * 128, 1024, tid);
        __syncthreads();
        mma128(acc, s_in, 260, kc, s_w, tx, ty);
    }
#pragma unroll
    for (int i = 0; i < 4; i++) {
        float p = 0.f;
#pragma unroll
        for (int j = 0; j < 8; j++) {
            int o = tx * 8 + j;
            p += siluf(acc[i][j] + s_vb1[o]) * s_vW2[o];
        }
#pragma unroll
        for (int off = 8; off >= 1; off >>= 1)
            p += __shfl_xor_sync(0xffffffffu, p, off);
        if (tx == 0) s_vel[ty * 4 + i] = p;
    }

    // ---- node layer 1: t = silu([h|m_i] @ nW1 + nb1), K=256 ----
#pragma unroll
    for (int i = 0; i < 4; i++)
#pragma unroll
        for (int j = 0; j < 8; j++) acc[i][j] = 0.f;
    for (int kc = 0; kc < 256; kc += 32) {
        __syncthreads();
        load_w(s_w, nW1 + kc * 128, 1024, tid);
        __syncthreads();
        mma128(acc, s_in, 260, kc, s_w, tx, ty);
    }
#pragma unroll
    for (int i = 0; i < 4; i++) {
        int e = ty * 4 + i;
#pragma unroll
        for (int j = 0; j < 8; j++) {
            int o = tx * 8 + j;
            s_t[e * 132 + o] = siluf(acc[i][j] + s_nb1[o]);
        }
    }

    // ---- node layer 2: h_out = t @ nW2 + nb2 ----
#pragma unroll
    for (int i = 0; i < 4; i++)
#pragma unroll
        for (int j = 0; j < 8; j++) acc[i][j] = 0.f;
    for (int kc = 0; kc < 128; kc += 32) {
        __syncthreads();
        load_w(s_w, nW2 + kc * 128, 1024, tid);
        __syncthreads();
        mma128(acc, s_t, 132, kc, s_w, tx, ty);
    }
#pragma unroll
    for (int i = 0; i < 4; i++) {
        int e = ty * 4 + i;
        if (e < nn) {
            size_t n = (size_t)(n0 + e);
            int o = tx * 8;
            float4 o0, o1;
            o0.x = acc[i][0] + s_nb2[o + 0];
            o0.y = acc[i][1] + s_nb2[o + 1];
            o0.z = acc[i][2] + s_nb2[o + 2];
            o0.w = acc[i][3] + s_nb2[o + 3];
            o1.x = acc[i][4] + s_nb2[o + 4];
            o1.y = acc[i][5] + s_nb2[o + 5];
            o1.z = acc[i][6] + s_nb2[o + 6];
            o1.w = acc[i][7] + s_nb2[o + 7];
            *(float4*)(out + n * 128 + o) = o0;
            *(float4*)(out + n * 128 + o + 4) = o1;
        }
    }

    __syncthreads();
    // ---- v_out, x_out ----
    if (tid < TE && tid < nn) {
        size_t n = (size_t)(n0 + tid);
        float vs = s_vel[tid];
        float v0 = vinit[n * 3 + 0] * vs;
        float v1 = vinit[n * 3 + 1] * vs;
        float v2 = vinit[n * 3 + 2] * vs;
        float* out_x = out + (size_t)N * 128;
        float* out_v = out_x + (size_t)N * 3;
        out_v[n * 3 + 0] = v0;
        out_v[n * 3 + 1] = v1;
        out_v[n * 3 + 2] = v2;
        float x0 = x[n * 3 + 0], x1 = x[n * 3 + 1], x2 = x[n * 3 + 2];
        if (hase[n]) {
            x0 += v0 + aggx[n * 3 + 0] * invNm1;
            x1 += v1 + aggx[n * 3 + 1] * invNm1;
            x2 += v2 + aggx[n * 3 + 2] * invNm1;
        }
        out_x[n * 3 + 0] = x0;
        out_x[n * 3 + 1] = x1;
        out_x[n * 3 + 2] = x2;
    }
}

// ============================================================================
// Launch
// ============================================================================
extern "C" void kernel_launch(void* const* d_in, const int* in_sizes, int n_in,
                              void* d_out, int out_size) {
    const float* h     = (const float*)d_in[0];
    const float* x     = (const float*)d_in[1];
    const float* eattr = (const float*)d_in[2];
    const float* vinit = (const float*)d_in[3];
    const int*   ei    = (const int*)d_in[4];
    const float* eW1 = (const float*)d_in[5];
    const float* eb1 = (const float*)d_in[6];
    const float* eW2 = (const float*)d_in[7];
    const float* eb2 = (const float*)d_in[8];
    const float* cW1 = (const float*)d_in[9];
    const float* cb1 = (const float*)d_in[10];
    const float* cW2 = (const float*)d_in[11];
    const float* iW1 = (const float*)d_in[12];
    const float* ib1 = (const float*)d_in[13];
    const float* iW2 = (const float*)d_in[14];
    const float* ib2 = (const float*)d_in[15];
    const float* nW1 = (const float*)d_in[16];
    const float* nb1 = (const float*)d_in[17];
    const float* nW2 = (const float*)d_in[18];
    const float* nb2 = (const float*)d_in[19];
    const float* vW1 = (const float*)d_in[20];
    const float* vb1 = (const float*)d_in[21];
    const float* vW2 = (const float*)d_in[22];

    const int N = in_sizes[0] / 128;
    const int E = in_sizes[2];
    float* out = (float*)d_out;
    const float invNm1 = 1.0f / (float)(N - 1);

    void *p_mi = nullptr, *p_ax = nullptr, *p_he = nullptr;
    cudaGetSymbolAddress(&p_mi, g_mi);
    cudaGetSymbolAddress(&p_ax, g_aggx);
    cudaGetSymbolAddress(&p_he, g_hase);
    cudaMemsetAsync(p_mi, 0, (size_t)N * 128 * sizeof(float));
    cudaMemsetAsync(p_ax, 0, (size_t)N * 3 * sizeof(float));
    cudaMemsetAsync(p_he, 0, (size_t)N * sizeof(int));

    const int e_smem = E_SMEM_FLOATS * 4;
    const int n_smem = N_SMEM_FLOATS * 4;
    cudaFuncSetAttribute(egnn_edge_kernel,
                         cudaFuncAttributeMaxDynamicSharedMemorySize, e_smem);
    cudaFuncSetAttribute(egnn_node_kernel,
                         cudaFuncAttributeMaxDynamicSharedMemorySize, n_smem);

    int eblocks = (E + TE - 1) / TE;
    egnn_edge_kernel<<<eblocks, NTHREADS, e_smem>>>(
        h, x, eattr, ei, eW1, eb1, eW2, eb2, cW1, cb1, cW2,
        iW1, ib1, iW2, ib2,
        (float*)p_mi, (float*)p_ax, (int*)p_he, E);

    int nblocks = (N + TE - 1) / TE;
    egnn_node_kernel<<<nblocks, NTHREADS, n_smem>>>(
        h, x, vinit, nW1, nb1, nW2, nb2, vW1, vb1, vW2,
        (const float*)p_mi, (const float*)p_ax, (const int*)p_he,
        out, N, invNm1);
}

// round 4
// speedup vs baseline: 3.2330x; 3.2330x over previous
#include <cuda_runtime.h>
#include <cstdint>

#define NTHREADS 256
#define MAXN 65536

// Scratch (__device__ globals per allocation-free rule)
__device__ float g_mi[(size_t)MAXN * 128];
__device__ float g_aggx[(size_t)MAXN * 3];
__device__ int   g_hase[MAXN];
__device__ float g_P[(size_t)MAXN * 128];   // h @ eW1[0:128]
__device__ float g_Q[(size_t)MAXN * 128];   // h @ eW1[128:256]

__device__ __forceinline__ float siluf(float v) { return v / (1.0f + __expf(-v)); }
__device__ __forceinline__ float sigmf(float v) { return 1.0f / (1.0f + __expf(-v)); }

// round fp32 -> tf32 (result readable as fp32 with truncated mantissa)
__device__ __forceinline__ float f2tf(float f) {
    uint32_t r;
    asm("cvt.rna.tf32.f32 %0, %1;" : "=r"(r) : "f"(f));
    return __uint_as_float(r);
}

__device__ __forceinline__ void mma_tf32(float (&d)[4], const uint32_t (&a)[4],
                                         uint32_t b0, uint32_t b1) {
    asm volatile(
        "mma.sync.aligned.m16n8k8.row.col.f32.tf32.tf32.f32 "
        "{%0,%1,%2,%3}, {%4,%5,%6,%7}, {%8,%9}, {%0,%1,%2,%3};"
        : "+f"(d[0]), "+f"(d[1]), "+f"(d[2]), "+f"(d[3])
        : "r"(a[0]), "r"(a[1]), "r"(a[2]), "r"(a[3]), "r"(b0), "r"(b1));
}

// Stage W^T (tf32) into smem: W is row-major [K][M]; sW[m*132 + k].
// M must be a power of two. Coalesced LDG (lanes = consecutive m), STS.128.
__device__ __forceinline__ void stage_wT(float* sW, const float* __restrict__ W,
                                         int Mmask, int Mshift, int K, int tid) {
    const int M = Mmask + 1;
    const int tasks = M * (K >> 2);
    for (int id = tid; id < tasks; id += NTHREADS) {
        int m = id & Mmask;
        int kq = id >> Mshift;
        int k0 = kq << 2;
        float4 v;
        v.x = f2tf(W[(size_t)(k0 + 0) * M + m]);
        v.y = f2tf(W[(size_t)(k0 + 1) * M + m]);
        v.z = f2tf(W[(size_t)(k0 + 2) * M + m]);
        v.w = f2tf(W[(size_t)(k0 + 3) * M + m]);
        ((float4*)(sW + m * 132))[kq] = v;
    }
}

// K=128 tf32 GEMM inner loop. sW: [M][132] = W^T tf32. sB: [n][132] acts tf32.
// Out (m, n): acc[mt][nt][{(g,2q),(g,2q+1),(g+8,2q),(g+8,2q+1)}]
template <int MT, int NT>
__device__ __forceinline__ void gemm128(const float* __restrict__ sW,
                                        const float* __restrict__ sB,
                                        float (&acc)[MT][NT][4],
                                        int m0, int e0, int lane) {
    const int g = lane >> 2, q = lane & 3;
#pragma unroll 4
    for (int kk = 0; kk < 128; kk += 8) {
        uint32_t a[MT][4];
#pragma unroll
        for (int mt = 0; mt < MT; mt++) {
            const float* pa = sW + (m0 + mt * 16 + g) * 132 + kk + q;
            a[mt][0] = __float_as_uint(pa[0]);
            a[mt][1] = __float_as_uint(pa[8 * 132]);
            a[mt][2] = __float_as_uint(pa[4]);
            a[mt][3] = __float_as_uint(pa[8 * 132 + 4]);
        }
#pragma unroll
        for (int nt = 0; nt < NT; nt++) {
            const float* pb = sB + (e0 + nt * 8 + g) * 132 + kk + q;
            uint32_t b0 = __float_as_uint(pb[0]);
            uint32_t b1 = __float_as_uint(pb[4]);
#pragma unroll
            for (int mt = 0; mt < MT; mt++) mma_tf32(acc[mt][nt], a[mt], b0, b1);
        }
    }
}

// ============================================================================
// PQ kernel: P = h @ eW1[0:128], Q = h @ eW1[128:256]  (raw fp32 outputs)
// ============================================================================
#define PQ_SMEM (33792 * 4)

__global__ __launch_bounds__(NTHREADS, 1)
void egnn_pq_kernel(const float* __restrict__ h, const float* __restrict__ eW1,
                    float* __restrict__ P, float* __restrict__ Q, int N) {
    extern __shared__ float sm[];
    float* s_h = sm;            // 128 x 132
    float* s_w = sm + 16896;    // 128 x 132

    const int tid = threadIdx.x;
    const int lane = tid & 31, wid = tid >> 5;
    const int wm = wid >> 2, wn = wid & 3;
    const int m0 = wm * 64, e0 = wn * 32;
    const int n0 = blockIdx.x * 128;

    // stage h tile (tf32), clamp node index
    for (int idx = tid; idx < 128 * 32; idx += NTHREADS) {
        int e = idx >> 5, k4 = idx & 31;
        int n = n0 + e; if (n >= N) n = N - 1;
        float4 v = ((const float4*)(h + (size_t)n * 128))[k4];
        v.x = f2tf(v.x); v.y = f2tf(v.y); v.z = f2tf(v.z); v.w = f2tf(v.w);
        ((float4*)(s_h + e * 132))[k4] = v;
    }

    for (int half = 0; half < 2; half++) {
        __syncthreads();
        stage_wT(s_w, eW1 + (size_t)half * 128 * 128, 127, 7, 128, tid);
        __syncthreads();
        float acc[4][4][4];
#pragma unroll
        for (int a = 0; a < 4; a++)
#pragma unroll
            for (int b = 0; b < 4; b++)
#pragma unroll
                for (int c = 0; c < 4; c++) acc[a][b][c] = 0.f;
        gemm128<4, 4>(s_w, s_h, acc, m0, e0, lane);

        float* out = half ? Q : P;
        const int g = lane >> 2, q = lane & 3;
#pragma unroll
        for (int mt = 0; mt < 4; mt++)
#pragma unroll
            for (int nt = 0; nt < 4; nt++) {
                int m = m0 + mt * 16 + g;
                int e = e0 + nt * 8 + 2 * q;
#pragma unroll
                for (int c = 0; c < 4; c++) {
                    int mm = m + ((c >> 1) ? 8 : 0);
                    int ee = e + (c & 1);
                    int n = n0 + ee;
                    if (n < N) out[(size_t)n * 128 + mm] = acc[mt][nt][c];
                }
            }
    }
}

// ============================================================================
// Edge kernel: t1 gather-add, GEMM2 (m_ij), coord head, inf head, scatters.
// Tile: 128 edges per block.
// ============================================================================
// smem floats: s_t 16896 | s_m 16896 | s_w 16896 | consts 2176
#define E_SMEM ((16896 * 3 + 2176) * 4)

__global__ __launch_bounds__(NTHREADS, 1)
void egnn_edge_kernel(const float* __restrict__ x, const float* __restrict__ eattr,
                      const int* __restrict__ ei,
                      const float* __restrict__ eW1, const float* __restrict__ eb1,
                      const float* __restrict__ eW2, const float* __restrict__ eb2,
                      const float* __restrict__ cW1, const float* __restrict__ cb1,
                      const float* __restrict__ cW2,
                      const float* __restrict__ iW1, const float* __restrict__ ib1,
                      const float* __restrict__ iW2, const float* __restrict__ ib2,
                      const float* __restrict__ P, const float* __restrict__ Q,
                      float* __restrict__ mi, float* __restrict__ aggx,
                      int* __restrict__ hase, int E) {
    extern __shared__ float sm[];
    float* s_t = sm;             // 128 x 132 (t1, tf32)
    float* s_m = sm + 16896;     // 128 x 132 (m_ij, tf32)
    float* s_w = sm + 33792;     // weights^T
    float* sc  = sm + 50688;
    float* s_b1   = sc;          float* s_w256 = sc + 128;
    float* s_w257 = sc + 256;    float* s_b2   = sc + 384;
    float* s_cb1  = sc + 512;    float* s_cW2  = sc + 640;
    float* s_ib1  = sc + 768;    float* s_iW2  = sc + 832;
    float* s_ds   = sc + 896;    float* s_ea   = sc + 1024;
    float* s_xd   = sc + 1152;   // 384
    float* s_phi  = sc + 1536;   float* s_red  = sc + 1664;
    float* s_eij  = sc + 1792;
    int*   s_row  = (int*)(sc + 1920);
    int*   s_col  = (int*)(sc + 2048);

    const int tid = threadIdx.x;
    const int lane = tid & 31, wid = tid >> 5;
    const int wm = wid >> 2, wn = wid & 3;
    const int m0 = wm * 64, e0w = wn * 32;
    const int g = lane >> 2, q = lane & 3;
    const int e0 = blockIdx.x * 128;

    // ---- stage constants + per-edge meta ----
    if (tid < 128) {
        s_b1[tid]   = eb1[tid];
        s_w256[tid] = eW1[256 * 128 + tid];
        s_w257[tid] = eW1[257 * 128 + tid];
        s_b2[tid]   = eb2[tid];
        s_cb1[tid]  = cb1[tid];
        s_cW2[tid]  = cW2[tid];
        s_phi[tid] = 0.f;
        s_red[tid] = 0.f;
        int e = tid;
        int r = 0, c = 0;
        float dsv = 0.f, eav = 0.f, dx = 0.f, dy = 0.f, dz = 0.f;
        if (e0 + e < E) {
            r = ei[e0 + e];
            c = ei[E + e0 + e];
            dx = x[r * 3 + 0] - x[c * 3 + 0];
            dy = x[r * 3 + 1] - x[c * 3 + 1];
            dz = x[r * 3 + 2] - x[c * 3 + 2];
            dsv = dx * dx + dy * dy + dz * dz;
            eav = eattr[e0 + e];
        }
        s_row[e] = r; s_col[e] = c; s_ds[e] = dsv; s_ea[e] = eav;
        s_xd[e * 3 + 0] = dx; s_xd[e * 3 + 1] = dy; s_xd[e * 3 + 2] = dz;
    } else if (tid < 192) {
        int t = tid - 128;
        if (t < 64) { s_ib1[t] = ib1[t]; s_iW2[t] = iW2[t]; }
    }
    __syncthreads();

    // ---- t1 = silu(P[row] + Q[col] + ds*w256 + ea*w257 + b1)  (tf32) ----
    {
        const int e = tid & 127, half = tid >> 7;
        const int r = s_row[e], c = s_col[e];
        const float ds = s_ds[e], ea = s_ea[e];
        const float4* pp = (const float4*)(P + (size_t)r * 128 + half * 64);
        const float4* pq = (const float4*)(Q + (size_t)c * 128 + half * 64);
        float4* pt = (float4*)(s_t + e * 132 + half * 64);
#pragma unroll
        for (int i = 0; i < 16; i++) {
            float4 a = pp[i], b = pq[i];
            int m = half * 64 + i * 4;
            float4 o;
            o.x = f2tf(siluf(a.x + b.x + ds * s_w256[m + 0] + ea * s_w257[m + 0] + s_b1[m + 0]));
            o.y = f2tf(siluf(a.y + b.y + ds * s_w256[m + 1] + ea * s_w257[m + 1] + s_b1[m + 1]));
            o.z = f2tf(siluf(a.z + b.z + ds * s_w256[m + 2] + ea * s_w257[m + 2] + s_b1[m + 2]));
            o.w = f2tf(siluf(a.w + b.w + ds * s_w256[m + 3] + ea * s_w257[m + 3] + s_b1[m + 3]));
            pt[i] = o;
        }
    }
    stage_wT(s_w, eW2, 127, 7, 128, tid);
    __syncthreads();

    // ---- GEMM2: m_ij = silu(t1 @ eW2 + b2) ----
    {
        float acc[4][4][4];
#pragma unroll
        for (int a = 0; a < 4; a++)
#pragma unroll
            for (int b = 0; b < 4; b++)
#pragma unroll
                for (int c = 0; c < 4; c++) acc[a][b][c] = 0.f;
        gemm128<4, 4>(s_w, s_t, acc, m0, e0w, lane);
#pragma unroll
        for (int mt = 0; mt < 4; mt++)
#pragma unroll
            for (int nt = 0; nt < 4; nt++) {
                int m = m0 + mt * 16 + g;
                int e = e0w + nt * 8 + 2 * q;
                s_m[(e)     * 132 + m]     = f2tf(siluf(acc[mt][nt][0] + s_b2[m]));
                s_m[(e + 1) * 132 + m]     = f2tf(siluf(acc[mt][nt][1] + s_b2[m]));
                s_m[(e)     * 132 + m + 8] = f2tf(siluf(acc[mt][nt][2] + s_b2[m + 8]));
                s_m[(e + 1) * 132 + m + 8] = f2tf(siluf(acc[mt][nt][3] + s_b2[m + 8]));
            }
    }
    __syncthreads();

    // ---- coord head: phi = silu(m @ cW1 + cb1) . cW2 ----
    stage_wT(s_w, cW1, 127, 7, 128, tid);
    __syncthreads();
    {
        float acc[4][4][4];
#pragma unroll
        for (int a = 0; a < 4; a++)
#pragma unroll
            for (int b = 0; b < 4; b++)
#pragma unroll
                for (int c = 0; c < 4; c++) acc[a][b][c] = 0.f;
        gemm128<4, 4>(s_w, s_m, acc, m0, e0w, lane);
#pragma unroll
        for (int nt = 0; nt < 4; nt++) {
            float p0 = 0.f, p1 = 0.f;
#pragma unroll
            for (int mt = 0; mt < 4; mt++) {
                int m = m0 + mt * 16 + g;
                p0 += siluf(acc[mt][nt][0] + s_cb1[m]) * s_cW2[m];
                p1 += siluf(acc[mt][nt][1] + s_cb1[m]) * s_cW2[m];
                p0 += siluf(acc[mt][nt][2] + s_cb1[m + 8]) * s_cW2[m + 8];
                p1 += siluf(acc[mt][nt][3] + s_cb1[m + 8]) * s_cW2[m + 8];
            }
#pragma unroll
            for (int off = 4; off <= 16; off <<= 1) {
                p0 += __shfl_xor_sync(0xffffffffu, p0, off);
                p1 += __shfl_xor_sync(0xffffffffu, p1, off);
            }
            if (g == 0) {
                atomicAdd(&s_phi[e0w + nt * 8 + 2 * q], p0);
                atomicAdd(&s_phi[e0w + nt * 8 + 2 * q + 1], p1);
            }
        }
    }
    __syncthreads();

    // ---- inf head (M=64): pre-sigmoid logit ----
    stage_wT(s_w, iW1, 63, 6, 128, tid);
    __syncthreads();
    {
        const int m0i = wm * 32;
        float acc[2][4][4];
#pragma unroll
        for (int a = 0; a < 2; a++)
#pragma unroll
            for (int b = 0; b < 4; b++)
#pragma unroll
                for (int c = 0; c < 4; c++) acc[a][b][c] = 0.f;
        gemm128<2, 4>(s_w, s_m, acc, m0i, e0w, lane);
#pragma unroll
        for (int nt = 0; nt < 4; nt++) {
            float p0 = 0.f, p1 = 0.f;
#pragma unroll
            for (int mt = 0; mt < 2; mt++) {
                int m = m0i + mt * 16 + g;
                p0 += siluf(acc[mt][nt][0] + s_ib1[m]) * s_iW2[m];
                p1 += siluf(acc[mt][nt][1] + s_ib1[m]) * s_iW2[m];
                p0 += siluf(acc[mt][nt][2] + s_ib1[m + 8]) * s_iW2[m + 8];
                p1 += siluf(acc[mt][nt][3] + s_ib1[m + 8]) * s_iW2[m + 8];
            }
#pragma unroll
            for (int off = 4; off <= 16; off <<= 1) {
                p0 += __shfl_xor_sync(0xffffffffu, p0, off);
                p1 += __shfl_xor_sync(0xffffffffu, p1, off);
            }
            if (g == 0) {
                atomicAdd(&s_red[e0w + nt * 8 + 2 * q], p0);
                atomicAdd(&s_red[e0w + nt * 8 + 2 * q + 1], p1);
            }
        }
    }
    __syncthreads();

    // ---- per-edge: e_ij, x_update scatter ----
    if (tid < 128) {
        int e = tid;
        float ev = sigmf(s_red[e] + __ldg(&ib2[0]));
        s_eij[e] = ev;
        if (e0 + e < E) {
            int r = s_row[e];
            float f = ev * s_phi[e];
            atomicAdd(&aggx[(size_t)r * 3 + 0], f * s_xd[e * 3 + 0]);
            atomicAdd(&aggx[(size_t)r * 3 + 1], f * s_xd[e * 3 + 1]);
            atomicAdd(&aggx[(size_t)r * 3 + 2], f * s_xd[e * 3 + 2]);
            hase[r] = 1;
        }
    }
    __syncthreads();

    // ---- m_i scatter: mi[row] += e_ij * m_ij  (vectorized RED) ----
    for (int idx = tid; idx < 128 * 32; idx += NTHREADS) {
        int e = idx >> 5, j4 = idx & 31;
        if (e0 + e < E) {
            float ev = s_eij[e];
            const float* pm = s_m + e * 132 + j4 * 4;
            float* dst = mi + (size_t)s_row[e] * 128 + j4 * 4;
            asm volatile("red.global.add.v4.f32 [%0], {%1,%2,%3,%4};"
                         :: "l"(dst), "f"(ev * pm[0]), "f"(ev * pm[1]),
                            "f"(ev * pm[2]), "f"(ev * pm[3]) : "memory");
        }
    }
}

// ============================================================================
// Node kernel: vel head, node MLP (K=256 in two passes), outputs.
// ============================================================================
#define N_SMEM ((16896 * 3 + 640) * 4)

__global__ __launch_bounds__(NTHREADS, 1)
void egnn_node_kernel(const float* __restrict__ h, const float* __restrict__ x,
                      const float* __restrict__ vinit,
                      const float* __restrict__ nW1, const float* __restrict__ nb1,
                      const float* __restrict__ nW2, const float* __restrict__ nb2,
                      const float* __restrict__ vW1, const float* __restrict__ vb1,
                      const float* __restrict__ vW2,
                      const float* __restrict__ mi, const float* __restrict__ aggx,
                      const int* __restrict__ hase,
                      float* __restrict__ out, int N, float invNm1) {
    extern __shared__ float sm[];
    float* s_a = sm;             // acts: h then m_i
    float* s_t = sm + 16896;
    float* s_w = sm + 33792;
    float* sc  = sm + 50688;
    float* s_nb1 = sc;           float* s_nb2 = sc + 128;
    float* s_vb1 = sc + 256;     float* s_vW2 = sc + 384;
    float* s_vel = sc + 512;     // 128

    const int tid = threadIdx.x;
    const int lane = tid & 31, wid = tid >> 5;
    const int wm = wid >> 2, wn = wid & 3;
    const int m0 = wm * 64, e0w = wn * 32;
    const int g = lane >> 2, q = lane & 3;
    const int n0 = blockIdx.x * 128;

    if (tid < 128) {
        s_nb1[tid] = nb1[tid]; s_nb2[tid] = nb2[tid];
        s_vb1[tid] = vb1[tid]; s_vW2[tid] = vW2[tid];
        s_vel[tid] = 0.f;
    }

    // stage h (tf32), clamped
    for (int idx = tid; idx < 128 * 32; idx += NTHREADS) {
        int e = idx >> 5, k4 = idx & 31;
        int n = n0 + e; if (n >= N) n = N - 1;
        float4 v = ((const float4*)(h + (size_t)n * 128))[k4];
        v.x = f2tf(v.x); v.y = f2tf(v.y); v.z = f2tf(v.z); v.w = f2tf(v.w);
        ((float4*)(s_a + e * 132))[k4] = v;
    }
    stage_wT(s_w, vW1, 127, 7, 128, tid);
    __syncthreads();

    // ---- vel head: scale = silu(h @ vW1 + vb1) . vW2 ----
    {
        float acc[4][4][4];
#pragma unroll
        for (int a = 0; a < 4; a++)
#pragma unroll
            for (int b = 0; b < 4; b++)
#pragma unroll
                for (int c = 0; c < 4; c++) acc[a][b][c] = 0.f;
        gemm128<4, 4>(s_w, s_a, acc, m0, e0w, lane);
#pragma unroll
        for (int nt = 0; nt < 4; nt++) {
            float p0 = 0.f, p1 = 0.f;
#pragma unroll
            for (int mt = 0; mt < 4; mt++) {
                int m = m0 + mt * 16 + g;
                p0 += siluf(acc[mt][nt][0] + s_vb1[m]) * s_vW2[m];
                p1 += siluf(acc[mt][nt][1] + s_vb1[m]) * s_vW2[m];
                p0 += siluf(acc[mt][nt][2] + s_vb1[m + 8]) * s_vW2[m + 8];
                p1 += siluf(acc[mt][nt][3] + s_vb1[m + 8]) * s_vW2[m + 8];
            }
#pragma unroll
            for (int off = 4; off <= 16; off <<= 1) {
                p0 += __shfl_xor_sync(0xffffffffu, p0, off);
                p1 += __shfl_xor_sync(0xffffffffu, p1, off);
            }
            if (g == 0) {
                atomicAdd(&s_vel[e0w + nt * 8 + 2 * q], p0);
                atomicAdd(&s_vel[e0w + nt * 8 + 2 * q + 1], p1);
            }
        }
    }
    __syncthreads();

    // ---- node layer 1: acc over [h | m_i] ----
    float accN[4][4][4];
#pragma unroll
    for (int a = 0; a < 4; a++)
#pragma unroll
        for (int b = 0; b < 4; b++)
#pragma unroll
            for (int c = 0; c < 4; c++) accN[a][b][c] = 0.f;

    stage_wT(s_w, nW1, 127, 7, 128, tid);         // nW1 rows 0..127 (h part)
    __syncthreads();
    gemm128<4, 4>(s_w, s_a, accN, m0, e0w, lane);
    __syncthreads();

    // restage s_a <- m_i, s_w <- nW1 rows 128..255
    for (int idx = tid; idx < 128 * 32; idx += NTHREADS) {
        int e = idx >> 5, k4 = idx & 31;
        int n = n0 + e; if (n >= N) n = N - 1;
        float4 v = ((const float4*)(mi + (size_t)n * 128))[k4];
        v.x = f2tf(v.x); v.y = f2tf(v.y); v.z = f2tf(v.z); v.w = f2tf(v.w);
        ((float4*)(s_a + e * 132))[k4] = v;
    }
    stage_wT(s_w, nW1 + (size_t)128 * 128, 127, 7, 128, tid);
    __syncthreads();
    gemm128<4, 4>(s_w, s_a, accN, m0, e0w, lane);

#pragma unroll
    for (int mt = 0; mt < 4; mt++)
#pragma unroll
        for (int nt = 0; nt < 4; nt++) {
            int m = m0 + mt * 16 + g;
            int e = e0w + nt * 8 + 2 * q;
            s_t[(e)     * 132 + m]     = f2tf(siluf(accN[mt][nt][0] + s_nb1[m]));
            s_t[(e + 1) * 132 + m]     = f2tf(siluf(accN[mt][nt][1] + s_nb1[m]));
            s_t[(e)     * 132 + m + 8] = f2tf(siluf(accN[mt][nt][2] + s_nb1[m + 8]));
            s_t[(e + 1) * 132 + m + 8] = f2tf(siluf(accN[mt][nt][3] + s_nb1[m + 8]));
        }
    __syncthreads();

    // ---- node layer 2: h_out = t @ nW2 + nb2 ----
    stage_wT(s_w, nW2, 127, 7, 128, tid);
    __syncthreads();
    {
        float acc[4][4][4];
#pragma unroll
        for (int a = 0; a < 4; a++)
#pragma unroll
            for (int b = 0; b < 4; b++)
#pragma unroll
                for (int c = 0; c < 4; c++) acc[a][b][c] = 0.f;
        gemm128<4, 4>(s_w, s_t, acc, m0, e0w, lane);
#pragma unroll
        for (int mt = 0; mt < 4; mt++)
#pragma unroll
            for (int nt = 0; nt < 4; nt++) {
                int m = m0 + mt * 16 + g;
                int e = e0w + nt * 8 + 2 * q;
#pragma unroll
                for (int c = 0; c < 4; c++) {
                    int mm = m + ((c >> 1) ? 8 : 0);
                    int ee = e + (c & 1);
                    int n = n0 + ee;
                    if (n < N)
                        out[(size_t)n * 128 + mm] = acc[mt][nt][c] + s_nb2[mm];
                }
            }
    }

    // ---- v_out, x_out ----
    if (tid < 128) {
        int n = n0 + tid;
        if (n < N) {
            float vs = s_vel[tid];
            float v0 = vinit[(size_t)n * 3 + 0] * vs;
            float v1 = vinit[(size_t)n * 3 + 1] * vs;
            float v2 = vinit[(size_t)n * 3 + 2] * vs;
            float* out_x = out + (size_t)N * 128;
            float* out_v = out_x + (size_t)N * 3;
            out_v[(size_t)n * 3 + 0] = v0;
            out_v[(size_t)n * 3 + 1] = v1;
            out_v[(size_t)n * 3 + 2] = v2;
            float x0 = x[(size_t)n * 3 + 0], x1 = x[(size_t)n * 3 + 1], x2 = x[(size_t)n * 3 + 2];
            if (hase[n]) {
                x0 += v0 + aggx[(size_t)n * 3 + 0] * invNm1;
                x1 += v1 + aggx[(size_t)n * 3 + 1] * invNm1;
                x2 += v2 + aggx[(size_t)n * 3 + 2] * invNm1;
            }
            out_x[(size_t)n * 3 + 0] = x0;
            out_x[(size_t)n * 3 + 1] = x1;
            out_x[(size_t)n * 3 + 2] = x2;
        }
    }
}

// ============================================================================
// Launch
// ============================================================================
extern "C" void kernel_launch(void* const* d_in, const int* in_sizes, int n_in,
                              void* d_out, int out_size) {
    const float* h     = (const float*)d_in[0];
    const float* x     = (const float*)d_in[1];
    const float* eattr = (const float*)d_in[2];
    const float* vinit = (const float*)d_in[3];
    const int*   ei    = (const int*)d_in[4];
    const float* eW1 = (const float*)d_in[5];
    const float* eb1 = (const float*)d_in[6];
    const float* eW2 = (const float*)d_in[7];
    const float* eb2 = (const float*)d_in[8];
    const float* cW1 = (const float*)d_in[9];
    const float* cb1 = (const float*)d_in[10];
    const float* cW2 = (const float*)d_in[11];
    const float* iW1 = (const float*)d_in[12];
    const float* ib1 = (const float*)d_in[13];
    const float* iW2 = (const float*)d_in[14];
    const float* ib2 = (const float*)d_in[15];
    const float* nW1 = (const float*)d_in[16];
    const float* nb1 = (const float*)d_in[17];
    const float* nW2 = (const float*)d_in[18];
    const float* nb2 = (const float*)d_in[19];
    const float* vW1 = (const float*)d_in[20];
    const float* vb1 = (const float*)d_in[21];
    const float* vW2 = (const float*)d_in[22];

    const int N = in_sizes[0] / 128;
    const int E = in_sizes[2];
    float* out = (float*)d_out;
    const float invNm1 = 1.0f / (float)(N - 1);

    void *p_mi, *p_ax, *p_he, *p_P, *p_Q;
    cudaGetSymbolAddress(&p_mi, g_mi);
    cudaGetSymbolAddress(&p_ax, g_aggx);
    cudaGetSymbolAddress(&p_he, g_hase);
    cudaGetSymbolAddress(&p_P, g_P);
    cudaGetSymbolAddress(&p_Q, g_Q);
    cudaMemsetAsync(p_mi, 0, (size_t)N * 128 * sizeof(float));
    cudaMemsetAsync(p_ax, 0, (size_t)N * 3 * sizeof(float));
    cudaMemsetAsync(p_he, 0, (size_t)N * sizeof(int));

    cudaFuncSetAttribute(egnn_pq_kernel,
                         cudaFuncAttributeMaxDynamicSharedMemorySize, PQ_SMEM);
    cudaFuncSetAttribute(egnn_edge_kernel,
                         cudaFuncAttributeMaxDynamicSharedMemorySize, E_SMEM);
    cudaFuncSetAttribute(egnn_node_kernel,
                         cudaFuncAttributeMaxDynamicSharedMemorySize, N_SMEM);

    int nblocks = (N + 127) / 128;
    egnn_pq_kernel<<<nblocks, NTHREADS, PQ_SMEM>>>(h, eW1, (float*)p_P, (float*)p_Q, N);

    int eblocks = (E + 127) / 128;
    egnn_edge_kernel<<<eblocks, NTHREADS, E_SMEM>>>(
        x, eattr, ei, eW1, eb1, eW2, eb2, cW1, cb1, cW2,
        iW1, ib1, iW2, ib2,
        (const float*)p_P, (const float*)p_Q,
        (float*)p_mi, (float*)p_ax, (int*)p_he, E);

    egnn_node_kernel<<<nblocks, NTHREADS, N_SMEM>>>(
        h, x, vinit, nW1, nb1, nW2, nb2, vW1, vb1, vW2,
        (const float*)p_mi, (const float*)p_ax, (const int*)p_he,
        out, N, invNm1);
}

// round 7
// speedup vs baseline: 3.6438x; 1.1271x over previous
#include <cuda_runtime.h>
#include <cstdint>

#define NTHREADS 256
#define MAXN 65536

// Scratch (__device__ globals per allocation-free rule)
__device__ float g_mi[(size_t)MAXN * 128];
__device__ float g_aggx[(size_t)MAXN * 3];
__device__ int   g_hase[MAXN];
__device__ float g_P[(size_t)MAXN * 128];   // h @ eW1[0:128]
__device__ float g_Q[(size_t)MAXN * 128];   // h @ eW1[128:256]

__device__ __forceinline__ float siluf(float v) { return v / (1.0f + __expf(-v)); }
__device__ __forceinline__ float sigmf(float v) { return 1.0f / (1.0f + __expf(-v)); }

__device__ __forceinline__ float f2tf(float f) {
    uint32_t r;
    asm("cvt.rna.tf32.f32 %0, %1;" : "=r"(r) : "f"(f));
    return __uint_as_float(r);
}

__device__ __forceinline__ void mma_tf32(float (&d)[4], const uint32_t (&a)[4],
                                         uint32_t b0, uint32_t b1) {
    asm volatile(
        "mma.sync.aligned.m16n8k8.row.col.f32.tf32.tf32.f32 "
        "{%0,%1,%2,%3}, {%4,%5,%6,%7}, {%8,%9}, {%0,%1,%2,%3};"
        : "+f"(d[0]), "+f"(d[1]), "+f"(d[2]), "+f"(d[3])
        : "r"(a[0]), "r"(a[1]), "r"(a[2]), "r"(a[3]), "r"(b0), "r"(b1));
}

// ============================================================================
// Swizzled (stride 128, XOR granule) layout helpers for the persistent kernel
// phys float index of (row, k): row*128 + (((k>>2) ^ (row&7))<<2) + (k&3)
// ============================================================================
__device__ __forceinline__ void stage_w_sw(float* sW, const float* __restrict__ W,
                                           int Mshift, int tid) {
    const int M = 1 << Mshift;
    const int tasks = M * 32;  // K=128 -> 32 float4 per m row
    for (int id = tid; id < tasks; id += NTHREADS) {
        int m = id & (M - 1);
        int kq = id >> Mshift;
        int k0 = kq << 2;
        float4 v;
        v.x = f2tf(W[(size_t)(k0 + 0) * M + m]);
        v.y = f2tf(W[(size_t)(k0 + 1) * M + m]);
        v.z = f2tf(W[(size_t)(k0 + 2) * M + m]);
        v.w = f2tf(W[(size_t)(k0 + 3) * M + m]);
        ((float4*)(sW + m * 128))[kq ^ (m & 7)] = v;
    }
}

template <int MT, int NT>
__device__ __forceinline__ void gemm_sw(const float* __restrict__ sW,
                                        const float* __restrict__ sA,
                                        float (&acc)[MT][NT][4],
                                        int m0, int e0, int g, int q) {
    int abase[MT], ax[MT];
#pragma unroll
    for (int mt = 0; mt < MT; mt++) {
        int r = m0 + mt * 16 + g;
        abase[mt] = r * 128 + q; ax[mt] = r & 7;
    }
    int bbase[NT], bx[NT];
#pragma unroll
    for (int nt = 0; nt < NT; nt++) {
        int r = e0 + nt * 8 + g;
        bbase[nt] = r * 128 + q; bx[nt] = r & 7;
    }
#pragma unroll 4
    for (int kk = 0; kk < 128; kk += 8) {
        const int kg = kk >> 2;       // even
        uint32_t a[MT][4];
#pragma unroll
        for (int mt = 0; mt < MT; mt++) {
            int off = (kg ^ ax[mt]) << 2;
            a[mt][0] = __float_as_uint(sW[abase[mt] + off]);
            a[mt][1] = __float_as_uint(sW[abase[mt] + 1024 + off]);
            a[mt][2] = __float_as_uint(sW[abase[mt] + (off ^ 4)]);
            a[mt][3] = __float_as_uint(sW[abase[mt] + 1024 + (off ^ 4)]);
        }
#pragma unroll
        for (int nt = 0; nt < NT; nt++) {
            int off = (kg ^ bx[nt]) << 2;
            uint32_t b0 = __float_as_uint(sA[bbase[nt] + off]);
            uint32_t b1 = __float_as_uint(sA[bbase[nt] + (off ^ 4)]);
#pragma unroll
            for (int mt = 0; mt < MT; mt++) mma_tf32(acc[mt][nt], a[mt], b0, b1);
        }
    }
}

// ============================================================================
// Padded-layout helpers (pq / node kernels)
// ============================================================================
__device__ __forceinline__ void stage_wT(float* sW, const float* __restrict__ W,
                                         int Mmask, int Mshift, int K, int tid) {
    const int M = Mmask + 1;
    const int tasks = M * (K >> 2);
    for (int id = tid; id < tasks; id += NTHREADS) {
        int m = id & Mmask;
        int kq = id >> Mshift;
        int k0 = kq << 2;
        float4 v;
        v.x = f2tf(W[(size_t)(k0 + 0) * M + m]);
        v.y = f2tf(W[(size_t)(k0 + 1) * M + m]);
        v.z = f2tf(W[(size_t)(k0 + 2) * M + m]);
        v.w = f2tf(W[(size_t)(k0 + 3) * M + m]);
        ((float4*)(sW + m * 132))[kq] = v;
    }
}

template <int MT, int NT>
__device__ __forceinline__ void gemm128(const float* __restrict__ sW,
                                        const float* __restrict__ sB,
                                        float (&acc)[MT][NT][4],
                                        int m0, int e0, int lane) {
    const int g = lane >> 2, q = lane & 3;
#pragma unroll 4
    for (int kk = 0; kk < 128; kk += 8) {
        uint32_t a[MT][4];
#pragma unroll
        for (int mt = 0; mt < MT; mt++) {
            const float* pa = sW + (m0 + mt * 16 + g) * 132 + kk + q;
            a[mt][0] = __float_as_uint(pa[0]);
            a[mt][1] = __float_as_uint(pa[8 * 132]);
            a[mt][2] = __float_as_uint(pa[4]);
            a[mt][3] = __float_as_uint(pa[8 * 132 + 4]);
        }
#pragma unroll
        for (int nt = 0; nt < NT; nt++) {
            const float* pb = sB + (e0 + nt * 8 + g) * 132 + kk + q;
            uint32_t b0 = __float_as_uint(pb[0]);
            uint32_t b1 = __float_as_uint(pb[4]);
#pragma unroll
            for (int mt = 0; mt < MT; mt++) mma_tf32(acc[mt][nt], a[mt], b0, b1);
        }
    }
}

// ============================================================================
// PQ kernel: P = h @ eW1[0:128], Q = h @ eW1[128:256]
// ============================================================================
#define PQ_SMEM (33792 * 4)

__global__ __launch_bounds__(NTHREADS, 1)
void egnn_pq_kernel(const float* __restrict__ h, const float* __restrict__ eW1,
                    float* __restrict__ P, float* __restrict__ Q, int N) {
    extern __shared__ float sm[];
    float* s_h = sm;
    float* s_w = sm + 16896;

    const int tid = threadIdx.x;
    const int lane = tid & 31, wid = tid >> 5;
    const int wm = wid >> 2, wn = wid & 3;
    const int m0 = wm * 64, e0 = wn * 32;
    const int n0 = blockIdx.x * 128;

    for (int idx = tid; idx < 128 * 32; idx += NTHREADS) {
        int e = idx >> 5, k4 = idx & 31;
        int n = n0 + e; if (n >= N) n = N - 1;
        float4 v = ((const float4*)(h + (size_t)n * 128))[k4];
        v.x = f2tf(v.x); v.y = f2tf(v.y); v.z = f2tf(v.z); v.w = f2tf(v.w);
        ((float4*)(s_h + e * 132))[k4] = v;
    }

    for (int half = 0; half < 2; half++) {
        __syncthreads();
        stage_wT(s_w, eW1 + (size_t)half * 128 * 128, 127, 7, 128, tid);
        __syncthreads();
        float acc[4][4][4];
#pragma unroll
        for (int a = 0; a < 4; a++)
#pragma unroll
            for (int b = 0; b < 4; b++)
#pragma unroll
                for (int c = 0; c < 4; c++) acc[a][b][c] = 0.f;
        gemm128<4, 4>(s_w, s_h, acc, m0, e0, lane);

        float* out = half ? Q : P;
        const int g = lane >> 2, q = lane & 3;
#pragma unroll
        for (int mt = 0; mt < 4; mt++)
#pragma unroll
            for (int nt = 0; nt < 4; nt++) {
                int m = m0 + mt * 16 + g;
                int e = e0 + nt * 8 + 2 * q;
#pragma unroll
                for (int c = 0; c < 4; c++) {
                    int mm = m + ((c >> 1) ? 8 : 0);
                    int ee = e + (c & 1);
                    int n = n0 + ee;
                    if (n < N) out[(size_t)n * 128 + mm] = acc[mt][nt][c];
                }
            }
    }
}

// ============================================================================
// Persistent edge kernel: weights resident in smem; loops over edge tiles.
// smem floats: s_w2 16384 | s_cw 16384 | s_iw 8192 | s_a 16384 | red 384
// total 57728 floats = 230912 B.  EGRID = 148 (one CTA per SM, 1 wave).
// ============================================================================
#define E_SMEM (57728 * 4)
#define EGRID 148

__global__ __launch_bounds__(NTHREADS, 1)
void egnn_edge_persist(const float* __restrict__ x, const float* __restrict__ eattr,
                       const int* __restrict__ ei,
                       const float* __restrict__ eW1, const float* __restrict__ eb1,
                       const float* __restrict__ eW2, const float* __restrict__ eb2,
                       const float* __restrict__ cW1, const float* __restrict__ cb1,
                       const float* __restrict__ cW2,
                       const float* __restrict__ iW1, const float* __restrict__ ib1,
                       const float* __restrict__ iW2, const float* __restrict__ ib2,
                       const float* __restrict__ P, const float* __restrict__ Q,
                       float* __restrict__ mi, float* __restrict__ aggx,
                       int* __restrict__ hase, int E, int ntiles) {
    extern __shared__ float sm[];
    float* s_w2  = sm;              // eW2^T  [128][128] swizzled
    float* s_cw  = sm + 16384;      // cW1^T  [128][128]
    float* s_iw  = sm + 32768;      // iW1^T  [64][128]
    float* s_a   = sm + 40960;      // acts   [128 edges][128] swizzled
    float* s_eij = sm + 57344;      // 128
    float* s_phi = sm + 57472;      // 128
    float* s_red = sm + 57600;      // 128

    const int tid = threadIdx.x;
    const int lane = tid & 31, wid = tid >> 5;
    const int wm = wid >> 2, wn = wid & 3;   // 2m x 4e warp grid
    const int g = lane >> 2, q = lane & 3;
    const int m0 = wm * 64;                  // MT=4 -> 64 m per warp
    const int e0w = wn * 32;                 // NT=4 -> 32 edges per warp

    stage_w_sw(s_w2, eW2, 7, tid);
    stage_w_sw(s_cw, cW1, 7, tid);
    stage_w_sw(s_iw, iW1, 6, tid);

    // per-thread epilogue constants
    float c_b2[8], c_cb1[8], c_cw2[8], c_ib1[4], c_iw2[4];
#pragma unroll
    for (int mt = 0; mt < 4; mt++) {
        int m = m0 + mt * 16 + g;
        c_b2[mt * 2]  = eb2[m];  c_b2[mt * 2 + 1]  = eb2[m + 8];
        c_cb1[mt * 2] = cb1[m];  c_cb1[mt * 2 + 1] = cb1[m + 8];
        c_cw2[mt * 2] = cW2[m];  c_cw2[mt * 2 + 1] = cW2[m + 8];
    }
#pragma unroll
    for (int mt = 0; mt < 2; mt++) {
        int m = wm * 32 + mt * 16 + g;
        c_ib1[mt * 2] = ib1[m]; c_ib1[mt * 2 + 1] = ib1[m + 8];
        c_iw2[mt * 2] = iW2[m]; c_iw2[mt * 2 + 1] = iW2[m + 8];
    }
    const float ib2v = ib2[0];
    __syncthreads();

    for (int t = blockIdx.x; t < ntiles; t += gridDim.x) {
        const int ebase = t * 128;

        // ---- build t1 = silu(P[row]+Q[col]+ds*w256+ea*w257+b1) into s_a ----
        {
            const int e = tid >> 1, half = tid & 1;
            const int ee = ebase + e;
            int r = 0, c = 0; float ds = 0.f, ea = 0.f;
            if (ee < E) {
                r = ei[ee]; c = ei[E + ee];
                float dx = x[r * 3 + 0] - x[c * 3 + 0];
                float dy = x[r * 3 + 1] - x[c * 3 + 1];
                float dz = x[r * 3 + 2] - x[c * 3 + 2];
                ds = dx * dx + dy * dy + dz * dz;
                ea = eattr[ee];
            }
            const float4* pp = (const float4*)(P + (size_t)r * 128) + half * 16;
            const float4* pq = (const float4*)(Q + (size_t)c * 128) + half * 16;
            const float4* pb1 = (const float4*)eb1 + half * 16;
            const float4* pw6 = (const float4*)(eW1 + 256 * 128) + half * 16;
            const float4* pw7 = (const float4*)(eW1 + 257 * 128) + half * 16;
            float4* prow = (float4*)(s_a + e * 128);
            const int x7 = e & 7;
#pragma unroll
            for (int i = 0; i < 16; i++) {
                float4 a = pp[i], b = pq[i];
                float4 w1 = __ldg(pb1 + i), w6 = __ldg(pw6 + i), w7 = __ldg(pw7 + i);
                float4 o;
                o.x = f2tf(siluf(a.x + b.x + ds * w6.x + ea * w7.x + w1.x));
                o.y = f2tf(siluf(a.y + b.y + ds * w6.y + ea * w7.y + w1.y));
                o.z = f2tf(siluf(a.z + b.z + ds * w6.z + ea * w7.z + w1.z));
                o.w = f2tf(siluf(a.w + b.w + ds * w6.w + ea * w7.w + w1.w));
                prow[(half * 16 + i) ^ x7] = o;
            }
        }
        __syncthreads();

        // ---- GEMM2: m = silu(t1 @ eW2 + b2) ----
        {
            float acc[4][4][4];
#pragma unroll
            for (int a = 0; a < 4; a++)
#pragma unroll
                for (int b = 0; b < 4; b++)
#pragma unroll
                    for (int c = 0; c < 4; c++) acc[a][b][c] = 0.f;
            gemm_sw<4, 4>(s_w2, s_a, acc, m0, e0w, g, q);
            __syncthreads();   // all reads of t1 complete
            if (tid < 128) { s_phi[tid] = 0.f; s_red[tid] = 0.f; }
#pragma unroll
            for (int mt = 0; mt < 4; mt++)
#pragma unroll
                for (int nt = 0; nt < 4; nt++) {
                    int m = m0 + mt * 16 + g;
                    int e = e0w + nt * 8 + 2 * q;
                    int gA = (m >> 2), gB = ((m + 8) >> 2);
                    int b0 = e * 128, b1r = (e + 1) * 128;
                    int e7a = e & 7, e7b = (e + 1) & 7;
                    int ml = m & 3;
                    s_a[b0  + (((gA ^ e7a) << 2) | ml)] =
                        f2tf(siluf(acc[mt][nt][0] + c_b2[mt * 2]));
                    s_a[b1r + (((gA ^ e7b) << 2) | ml)] =
                        f2tf(siluf(acc[mt][nt][1] + c_b2[mt * 2]));
                    s_a[b0  + (((gB ^ e7a) << 2) | ml)] =
                        f2tf(siluf(acc[mt][nt][2] + c_b2[mt * 2 + 1]));
                    s_a[b1r + (((gB ^ e7b) << 2) | ml)] =
                        f2tf(siluf(acc[mt][nt][3] + c_b2[mt * 2 + 1]));
                }
        }
        __syncthreads();

        // ---- coord head: phi = silu(m @ cW1 + cb1) . cW2 ----
        {
            float acc[4][4][4];
#pragma unroll
            for (int a = 0; a < 4; a++)
#pragma unroll
                for (int b = 0; b < 4; b++)
#pragma unroll
                    for (int c = 0; c < 4; c++) acc[a][b][c] = 0.f;
            gemm_sw<4, 4>(s_cw, s_a, acc, m0, e0w, g, q);
#pragma unroll
            for (int nt = 0; nt < 4; nt++) {
                float p0 = 0.f, p1 = 0.f;
#pragma unroll
                for (int mt = 0; mt < 4; mt++) {
                    p0 += siluf(acc[mt][nt][0] + c_cb1[mt * 2]) * c_cw2[mt * 2];
                    p1 += siluf(acc[mt][nt][1] + c_cb1[mt * 2]) * c_cw2[mt * 2];
                    p0 += siluf(acc[mt][nt][2] + c_cb1[mt * 2 + 1]) * c_cw2[mt * 2 + 1];
                    p1 += siluf(acc[mt][nt][3] + c_cb1[mt * 2 + 1]) * c_cw2[mt * 2 + 1];
                }
#pragma unroll
                for (int off = 4; off <= 16; off <<= 1) {
                    p0 += __shfl_xor_sync(0xffffffffu, p0, off);
                    p1 += __shfl_xor_sync(0xffffffffu, p1, off);
                }
                if (g == 0) {
                    atomicAdd(&s_phi[e0w + nt * 8 + 2 * q], p0);
                    atomicAdd(&s_phi[e0w + nt * 8 + 2 * q + 1], p1);
                }
            }
        }

        // ---- inf head (M=64): logit ----
        {
            float acc[2][4][4];
#pragma unroll
            for (int a = 0; a < 2; a++)
#pragma unroll
                for (int b = 0; b < 4; b++)
#pragma unroll
                    for (int c = 0; c < 4; c++) acc[a][b][c] = 0.f;
            gemm_sw<2, 4>(s_iw, s_a, acc, wm * 32, e0w, g, q);
#pragma unroll
            for (int nt = 0; nt < 4; nt++) {
                float p0 = 0.f, p1 = 0.f;
#pragma unroll
                for (int mt = 0; mt < 2; mt++) {
                    p0 += siluf(acc[mt][nt][0] + c_ib1[mt * 2]) * c_iw2[mt * 2];
                    p1 += siluf(acc[mt][nt][1] + c_ib1[mt * 2]) * c_iw2[mt * 2];
                    p0 += siluf(acc[mt][nt][2] + c_ib1[mt * 2 + 1]) * c_iw2[mt * 2 + 1];
                    p1 += siluf(acc[mt][nt][3] + c_ib1[mt * 2 + 1]) * c_iw2[mt * 2 + 1];
                }
#pragma unroll
                for (int off = 4; off <= 16; off <<= 1) {
                    p0 += __shfl_xor_sync(0xffffffffu, p0, off);
                    p1 += __shfl_xor_sync(0xffffffffu, p1, off);
                }
                if (g == 0) {
                    atomicAdd(&s_red[e0w + nt * 8 + 2 * q], p0);
                    atomicAdd(&s_red[e0w + nt * 8 + 2 * q + 1], p1);
                }
            }
        }
        __syncthreads();

        // ---- e_ij + x_update scatter ----
        if (tid < 128) {
            const int e = tid, ee = ebase + e;
            float ev = sigmf(s_red[e] + ib2v);
            s_eij[e] = ev;
            if (ee < E) {
                int r = ei[ee], c = ei[E + ee];
                float dx = x[r * 3 + 0] - x[c * 3 + 0];
                float dy = x[r * 3 + 1] - x[c * 3 + 1];
                float dz = x[r * 3 + 2] - x[c * 3 + 2];
                float f = ev * s_phi[e];
                atomicAdd(&aggx[(size_t)r * 3 + 0], f * dx);
                atomicAdd(&aggx[(size_t)r * 3 + 1], f * dy);
                atomicAdd(&aggx[(size_t)r * 3 + 2], f * dz);
                hase[r] = 1;
            }
        }
        __syncthreads();

        // ---- mi scatter: mi[row] += e_ij * m  ----
        for (int idx = tid; idx < 128 * 32; idx += NTHREADS) {
            int e = idx >> 5, j4 = idx & 31;
            int ee = ebase + e;
            if (ee < E) {
                float ev = s_eij[e];
                float4 v = ((const float4*)(s_a + e * 128))[j4 ^ (e & 7)];
                float* dst = mi + (size_t)ei[ee] * 128 + j4 * 4;
                asm volatile("red.global.add.v4.f32 [%0], {%1,%2,%3,%4};"
                             :: "l"(dst), "f"(ev * v.x), "f"(ev * v.y),
                                "f"(ev * v.z), "f"(ev * v.w) : "memory");
            }
        }
        __syncthreads();  // protect s_a / s_eij before next tile overwrites
    }
}

// ============================================================================
// Node kernel: vel head, node MLP (K=256 in two passes), outputs.
// ============================================================================
#define N_SMEM ((16896 * 3 + 640) * 4)

__global__ __launch_bounds__(NTHREADS, 1)
void egnn_node_kernel(const float* __restrict__ h, const float* __restrict__ x,
                      const float* __restrict__ vinit,
                      const float* __restrict__ nW1, const float* __restrict__ nb1,
                      const float* __restrict__ nW2, const float* __restrict__ nb2,
                      const float* __restrict__ vW1, const float* __restrict__ vb1,
                      const float* __restrict__ vW2,
                      const float* __restrict__ mi, const float* __restrict__ aggx,
                      const int* __restrict__ hase,
                      float* __restrict__ out, int N, float invNm1) {
    extern __shared__ float sm[];
    float* s_a = sm;
    float* s_t = sm + 16896;
    float* s_w = sm + 33792;
    float* sc  = sm + 50688;
    float* s_nb1 = sc;           float* s_nb2 = sc + 128;
    float* s_vb1 = sc + 256;     float* s_vW2 = sc + 384;
    float* s_vel = sc + 512;

    const int tid = threadIdx.x;
    const int lane = tid & 31, wid = tid >> 5;
    const int wm = wid >> 2, wn = wid & 3;
    const int m0 = wm * 64, e0w = wn * 32;
    const int g = lane >> 2, q = lane & 3;
    const int n0 = blockIdx.x * 128;

    if (tid < 128) {
        s_nb1[tid] = nb1[tid]; s_nb2[tid] = nb2[tid];
        s_vb1[tid] = vb1[tid]; s_vW2[tid] = vW2[tid];
        s_vel[tid] = 0.f;
    }

    for (int idx = tid; idx < 128 * 32; idx += NTHREADS) {
        int e = idx >> 5, k4 = idx & 31;
        int n = n0 + e; if (n >= N) n = N - 1;
        float4 v = ((const float4*)(h + (size_t)n * 128))[k4];
        v.x = f2tf(v.x); v.y = f2tf(v.y); v.z = f2tf(v.z); v.w = f2tf(v.w);
        ((float4*)(s_a + e * 132))[k4] = v;
    }
    stage_wT(s_w, vW1, 127, 7, 128, tid);
    __syncthreads();

    // vel head
    {
        float acc[4][4][4];
#pragma unroll
        for (int a = 0; a < 4; a++)
#pragma unroll
            for (int b = 0; b < 4; b++)
#pragma unroll
                for (int c = 0; c < 4; c++) acc[a][b][c] = 0.f;
        gemm128<4, 4>(s_w, s_a, acc, m0, e0w, lane);
#pragma unroll
        for (int nt = 0; nt < 4; nt++) {
            float p0 = 0.f, p1 = 0.f;
#pragma unroll
            for (int mt = 0; mt < 4; mt++) {
                int m = m0 + mt * 16 + g;
                p0 += siluf(acc[mt][nt][0] + s_vb1[m]) * s_vW2[m];
                p1 += siluf(acc[mt][nt][1] + s_vb1[m]) * s_vW2[m];
                p0 += siluf(acc[mt][nt][2] + s_vb1[m + 8]) * s_vW2[m + 8];
                p1 += siluf(acc[mt][nt][3] + s_vb1[m + 8]) * s_vW2[m + 8];
            }
#pragma unroll
            for (int off = 4; off <= 16; off <<= 1) {
                p0 += __shfl_xor_sync(0xffffffffu, p0, off);
                p1 += __shfl_xor_sync(0xffffffffu, p1, off);
            }
            if (g == 0) {
                atomicAdd(&s_vel[e0w + nt * 8 + 2 * q], p0);
                atomicAdd(&s_vel[e0w + nt * 8 + 2 * q + 1], p1);
            }
        }
    }
    __syncthreads();

    // node layer 1 over [h | m_i]
    float accN[4][4][4];
#pragma unroll
    for (int a = 0; a < 4; a++)
#pragma unroll
        for (int b = 0; b < 4; b++)
#pragma unroll
            for (int c = 0; c < 4; c++) accN[a][b][c] = 0.f;

    stage_wT(s_w, nW1, 127, 7, 128, tid);
    __syncthreads();
    gemm128<4, 4>(s_w, s_a, accN, m0, e0w, lane);
    __syncthreads();

    for (int idx = tid; idx < 128 * 32; idx += NTHREADS) {
        int e = idx >> 5, k4 = idx & 31;
        int n = n0 + e; if (n >= N) n = N - 1;
        float4 v = ((const float4*)(mi + (size_t)n * 128))[k4];
        v.x = f2tf(v.x); v.y = f2tf(v.y); v.z = f2tf(v.z); v.w = f2tf(v.w);
        ((float4*)(s_a + e * 132))[k4] = v;
    }
    stage_wT(s_w, nW1 + (size_t)128 * 128, 127, 7, 128, tid);
    __syncthreads();
    gemm128<4, 4>(s_w, s_a, accN, m0, e0w, lane);

#pragma unroll
    for (int mt = 0; mt < 4; mt++)
#pragma unroll
        for (int nt = 0; nt < 4; nt++) {
            int m = m0 + mt * 16 + g;
            int e = e0w + nt * 8 + 2 * q;
            s_t[(e)     * 132 + m]     = f2tf(siluf(accN[mt][nt][0] + s_nb1[m]));
            s_t[(e + 1) * 132 + m]     = f2tf(siluf(accN[mt][nt][1] + s_nb1[m]));
            s_t[(e)     * 132 + m + 8] = f2tf(siluf(accN[mt][nt][2] + s_nb1[m + 8]));
            s_t[(e + 1) * 132 + m + 8] = f2tf(siluf(accN[mt][nt][3] + s_nb1[m + 8]));
        }
    __syncthreads();

    // node layer 2
    stage_wT(s_w, nW2, 127, 7, 128, tid);
    __syncthreads();
    {
        float acc[4][4][4];
#pragma unroll
        for (int a = 0; a < 4; a++)
#pragma unroll
            for (int b = 0; b < 4; b++)
#pragma unroll
                for (int c = 0; c < 4; c++) acc[a][b][c] = 0.f;
        gemm128<4, 4>(s_w, s_t, acc, m0, e0w, lane);
#pragma unroll
        for (int mt = 0; mt < 4; mt++)
#pragma unroll
            for (int nt = 0; nt < 4; nt++) {
                int m = m0 + mt * 16 + g;
                int e = e0w + nt * 8 + 2 * q;
#pragma unroll
                for (int c = 0; c < 4; c++) {
                    int mm = m + ((c >> 1) ? 8 : 0);
                    int ee = e + (c & 1);
                    int n = n0 + ee;
                    if (n < N)
                        out[(size_t)n * 128 + mm] = acc[mt][nt][c] + s_nb2[mm];
                }
            }
    }

    if (tid < 128) {
        int n = n0 + tid;
        if (n < N) {
            float vs = s_vel[tid];
            float v0 = vinit[(size_t)n * 3 + 0] * vs;
            float v1 = vinit[(size_t)n * 3 + 1] * vs;
            float v2 = vinit[(size_t)n * 3 + 2] * vs;
            float* out_x = out + (size_t)N * 128;
            float* out_v = out_x + (size_t)N * 3;
            out_v[(size_t)n * 3 + 0] = v0;
            out_v[(size_t)n * 3 + 1] = v1;
            out_v[(size_t)n * 3 + 2] = v2;
            float x0 = x[(size_t)n * 3 + 0], x1 = x[(size_t)n * 3 + 1], x2 = x[(size_t)n * 3 + 2];
            if (hase[n]) {
                x0 += v0 + aggx[(size_t)n * 3 + 0] * invNm1;
                x1 += v1 + aggx[(size_t)n * 3 + 1] * invNm1;
                x2 += v2 + aggx[(size_t)n * 3 + 2] * invNm1;
            }
            out_x[(size_t)n * 3 + 0] = x0;
            out_x[(size_t)n * 3 + 1] = x1;
            out_x[(size_t)n * 3 + 2] = x2;
        }
    }
}

// ============================================================================
// Launch
// ============================================================================
extern "C" void kernel_launch(void* const* d_in, const int* in_sizes, int n_in,
                              void* d_out, int out_size) {
    const float* h     = (const float*)d_in[0];
    const float* x     = (const float*)d_in[1];
    const float* eattr = (const float*)d_in[2];
    const float* vinit = (const float*)d_in[3];
    const int*   ei    = (const int*)d_in[4];
    const float* eW1 = (const float*)d_in[5];
    const float* eb1 = (const float*)d_in[6];
    const float* eW2 = (const float*)d_in[7];
    const float* eb2 = (const float*)d_in[8];
    const float* cW1 = (const float*)d_in[9];
    const float* cb1 = (const float*)d_in[10];
    const float* cW2 = (const float*)d_in[11];
    const float* iW1 = (const float*)d_in[12];
    const float* ib1 = (const float*)d_in[13];
    const float* iW2 = (const float*)d_in[14];
    const float* ib2 = (const float*)d_in[15];
    const float* nW1 = (const float*)d_in[16];
    const float* nb1 = (const float*)d_in[17];
    const float* nW2 = (const float*)d_in[18];
    const float* nb2 = (const float*)d_in[19];
    const float* vW1 = (const float*)d_in[20];
    const float* vb1 = (const float*)d_in[21];
    const float* vW2 = (const float*)d_in[22];

    const int N = in_sizes[0] / 128;
    const int E = in_sizes[2];
    float* out = (float*)d_out;
    const float invNm1 = 1.0f / (float)(N - 1);

    void *p_mi, *p_ax, *p_he, *p_P, *p_Q;
    cudaGetSymbolAddress(&p_mi, g_mi);
    cudaGetSymbolAddress(&p_ax, g_aggx);
    cudaGetSymbolAddress(&p_he, g_hase);
    cudaGetSymbolAddress(&p_P, g_P);
    cudaGetSymbolAddress(&p_Q, g_Q);
    cudaMemsetAsync(p_mi, 0, (size_t)N * 128 * sizeof(float));
    cudaMemsetAsync(p_ax, 0, (size_t)N * 3 * sizeof(float));
    cudaMemsetAsync(p_he, 0, (size_t)N * sizeof(int));

    cudaFuncSetAttribute(egnn_pq_kernel,
                         cudaFuncAttributeMaxDynamicSharedMemorySize, PQ_SMEM);
    cudaFuncSetAttribute(egnn_edge_persist,
                         cudaFuncAttributeMaxDynamicSharedMemorySize, E_SMEM);
    cudaFuncSetAttribute(egnn_node_kernel,
                         cudaFuncAttributeMaxDynamicSharedMemorySize, N_SMEM);

    int nblocks = (N + 127) / 128;
    egnn_pq_kernel<<<nblocks, NTHREADS, PQ_SMEM>>>(h, eW1, (float*)p_P, (float*)p_Q, N);

    int ntiles = (E + 127) / 128;
    egnn_edge_persist<<<EGRID, NTHREADS, E_SMEM>>>(
        x, eattr, ei, eW1, eb1, eW2, eb2, cW1, cb1, cW2,
        iW1, ib1, iW2, ib2,
        (const float*)p_P, (const float*)p_Q,
        (float*)p_mi, (float*)p_ax, (int*)p_he, E, ntiles);

    egnn_node_kernel<<<nblocks, NTHREADS, N_SMEM>>>(
        h, x, vinit, nW1, nb1, nW2, nb2, vW1, vb1, vW2,
        (const float*)p_mi, (const float*)p_ax, (const int*)p_he,
        out, N, invNm1);
}

// round 8
// speedup vs baseline: 4.2907x; 1.1775x over previous
#include <cuda_runtime.h>
#include <cstdint>

#define PQTHREADS 256
#define WTHREADS 512
#define MAXN 65536

// Scratch (__device__ globals per allocation-free rule)
__device__ float g_mi[(size_t)MAXN * 128];
__device__ float g_aggx[(size_t)MAXN * 3];
__device__ int   g_hase[MAXN];
__device__ float g_P[(size_t)MAXN * 128];   // h @ eW1[0:128]
__device__ float g_Q[(size_t)MAXN * 128];   // h @ eW1[128:256]

__device__ __forceinline__ float siluf(float v) { return v / (1.0f + __expf(-v)); }
__device__ __forceinline__ float sigmf(float v) { return 1.0f / (1.0f + __expf(-v)); }

__device__ __forceinline__ float f2tf(float f) {
    uint32_t r;
    asm("cvt.rna.tf32.f32 %0, %1;" : "=r"(r) : "f"(f));
    return __uint_as_float(r);
}

__device__ __forceinline__ void mma_tf32(float (&d)[4], const uint32_t (&a)[4],
                                         uint32_t b0, uint32_t b1) {
    asm volatile(
        "mma.sync.aligned.m16n8k8.row.col.f32.tf32.tf32.f32 "
        "{%0,%1,%2,%3}, {%4,%5,%6,%7}, {%8,%9}, {%0,%1,%2,%3};"
        : "+f"(d[0]), "+f"(d[1]), "+f"(d[2]), "+f"(d[3])
        : "r"(a[0]), "r"(a[1]), "r"(a[2]), "r"(a[3]), "r"(b0), "r"(b1));
}

// ============================================================================
// Swizzled (stride 128, XOR granule) layout helpers
// phys float index of (row, k): row*128 + (((k>>2) ^ (row&7))<<2) + (k&3)
// ============================================================================
__device__ __forceinline__ void stage_w_sw(float* sW, const float* __restrict__ W,
                                           int Mshift, int tid, int nthr) {
    const int M = 1 << Mshift;
    const int tasks = M * 32;  // K=128 -> 32 float4 per m row
    for (int id = tid; id < tasks; id += nthr) {
        int m = id & (M - 1);
        int kq = id >> Mshift;
        int k0 = kq << 2;
        float4 v;
        v.x = f2tf(W[(size_t)(k0 + 0) * M + m]);
        v.y = f2tf(W[(size_t)(k0 + 1) * M + m]);
        v.z = f2tf(W[(size_t)(k0 + 2) * M + m]);
        v.w = f2tf(W[(size_t)(k0 + 3) * M + m]);
        ((float4*)(sW + m * 128))[kq ^ (m & 7)] = v;
    }
}

template <int MT, int NT>
__device__ __forceinline__ void gemm_sw(const float* __restrict__ sW,
                                        const float* __restrict__ sA,
                                        float (&acc)[MT][NT][4],
                                        int m0, int e0, int g, int q) {
    int abase[MT], ax[MT];
#pragma unroll
    for (int mt = 0; mt < MT; mt++) {
        int r = m0 + mt * 16 + g;
        abase[mt] = r * 128 + q; ax[mt] = r & 7;
    }
    int bbase[NT], bx[NT];
#pragma unroll
    for (int nt = 0; nt < NT; nt++) {
        int r = e0 + nt * 8 + g;
        bbase[nt] = r * 128 + q; bx[nt] = r & 7;
    }
#pragma unroll 4
    for (int kk = 0; kk < 128; kk += 8) {
        const int kg = kk >> 2;       // even
        uint32_t a[MT][4];
#pragma unroll
        for (int mt = 0; mt < MT; mt++) {
            int off = (kg ^ ax[mt]) << 2;
            a[mt][0] = __float_as_uint(sW[abase[mt] + off]);
            a[mt][1] = __float_as_uint(sW[abase[mt] + 1024 + off]);
            a[mt][2] = __float_as_uint(sW[abase[mt] + (off ^ 4)]);
            a[mt][3] = __float_as_uint(sW[abase[mt] + 1024 + (off ^ 4)]);
        }
#pragma unroll
        for (int nt = 0; nt < NT; nt++) {
            int off = (kg ^ bx[nt]) << 2;
            uint32_t b0 = __float_as_uint(sA[bbase[nt] + off]);
            uint32_t b1 = __float_as_uint(sA[bbase[nt] + (off ^ 4)]);
#pragma unroll
            for (int mt = 0; mt < MT; mt++) mma_tf32(acc[mt][nt], a[mt], b0, b1);
        }
    }
}

// ============================================================================
// Padded-layout helpers (pq / node kernels)
// ============================================================================
__device__ __forceinline__ void stage_wT(float* sW, const float* __restrict__ W,
                                         int Mmask, int Mshift, int K, int tid, int nthr) {
    const int M = Mmask + 1;
    const int tasks = M * (K >> 2);
    for (int id = tid; id < tasks; id += nthr) {
        int m = id & Mmask;
        int kq = id >> Mshift;
        int k0 = kq << 2;
        float4 v;
        v.x = f2tf(W[(size_t)(k0 + 0) * M + m]);
        v.y = f2tf(W[(size_t)(k0 + 1) * M + m]);
        v.z = f2tf(W[(size_t)(k0 + 2) * M + m]);
        v.w = f2tf(W[(size_t)(k0 + 3) * M + m]);
        ((float4*)(sW + m * 132))[kq] = v;
    }
}

template <int MT, int NT>
__device__ __forceinline__ void gemm128(const float* __restrict__ sW,
                                        const float* __restrict__ sB,
                                        float (&acc)[MT][NT][4],
                                        int m0, int e0, int lane) {
    const int g = lane >> 2, q = lane & 3;
#pragma unroll 4
    for (int kk = 0; kk < 128; kk += 8) {
        uint32_t a[MT][4];
#pragma unroll
        for (int mt = 0; mt < MT; mt++) {
            const float* pa = sW + (m0 + mt * 16 + g) * 132 + kk + q;
            a[mt][0] = __float_as_uint(pa[0]);
            a[mt][1] = __float_as_uint(pa[8 * 132]);
            a[mt][2] = __float_as_uint(pa[4]);
            a[mt][3] = __float_as_uint(pa[8 * 132 + 4]);
        }
#pragma unroll
        for (int nt = 0; nt < NT; nt++) {
            const float* pb = sB + (e0 + nt * 8 + g) * 132 + kk + q;
            uint32_t b0 = __float_as_uint(pb[0]);
            uint32_t b1 = __float_as_uint(pb[4]);
#pragma unroll
            for (int mt = 0; mt < MT; mt++) mma_tf32(acc[mt][nt], a[mt], b0, b1);
        }
    }
}

// ============================================================================
// PQ kernel: P = h @ eW1[0:128], Q = h @ eW1[128:256]   (256 threads)
// ============================================================================
#define PQ_SMEM (33792 * 4)

__global__ __launch_bounds__(PQTHREADS, 1)
void egnn_pq_kernel(const float* __restrict__ h, const float* __restrict__ eW1,
                    float* __restrict__ P, float* __restrict__ Q, int N) {
    extern __shared__ float sm[];
    float* s_h = sm;
    float* s_w = sm + 16896;

    const int tid = threadIdx.x;
    const int lane = tid & 31, wid = tid >> 5;
    const int wm = wid >> 2, wn = wid & 3;
    const int m0 = wm * 64, e0 = wn * 32;
    const int n0 = blockIdx.x * 128;

    for (int idx = tid; idx < 128 * 32; idx += PQTHREADS) {
        int e = idx >> 5, k4 = idx & 31;
        int n = n0 + e; if (n >= N) n = N - 1;
        float4 v = ((const float4*)(h + (size_t)n * 128))[k4];
        v.x = f2tf(v.x); v.y = f2tf(v.y); v.z = f2tf(v.z); v.w = f2tf(v.w);
        ((float4*)(s_h + e * 132))[k4] = v;
    }

    for (int half = 0; half < 2; half++) {
        __syncthreads();
        stage_wT(s_w, eW1 + (size_t)half * 128 * 128, 127, 7, 128, tid, PQTHREADS);
        __syncthreads();
        float acc[4][4][4];
#pragma unroll
        for (int a = 0; a < 4; a++)
#pragma unroll
            for (int b = 0; b < 4; b++)
#pragma unroll
                for (int c = 0; c < 4; c++) acc[a][b][c] = 0.f;
        gemm128<4, 4>(s_w, s_h, acc, m0, e0, lane);

        float* out = half ? Q : P;
        const int g = lane >> 2, q = lane & 3;
#pragma unroll
        for (int mt = 0; mt < 4; mt++)
#pragma unroll
            for (int nt = 0; nt < 4; nt++) {
                int m = m0 + mt * 16 + g;
                int e = e0 + nt * 8 + 2 * q;
#pragma unroll
                for (int c = 0; c < 4; c++) {
                    int mm = m + ((c >> 1) ? 8 : 0);
                    int ee = e + (c & 1);
                    int n = n0 + ee;
                    if (n < N) out[(size_t)n * 128 + mm] = acc[mt][nt][c];
                }
            }
    }
}

// ============================================================================
// Persistent edge kernel, 512 threads (16 warps, 4m x 4n, MT=2/NT=4).
// smem floats: s_w2 16384 | s_cw 16384 | s_iw 8192 | s_a 16384 | red 384
// ============================================================================
#define E_SMEM (57728 * 4)
#define EGRID 148

__global__ __launch_bounds__(WTHREADS, 1)
void egnn_edge_persist(const float* __restrict__ x, const float* __restrict__ eattr,
                       const int* __restrict__ ei,
                       const float* __restrict__ eW1, const float* __restrict__ eb1,
                       const float* __restrict__ eW2, const float* __restrict__ eb2,
                       const float* __restrict__ cW1, const float* __restrict__ cb1,
                       const float* __restrict__ cW2,
                       const float* __restrict__ iW1, const float* __restrict__ ib1,
                       const float* __restrict__ iW2, const float* __restrict__ ib2,
                       const float* __restrict__ P, const float* __restrict__ Q,
                       float* __restrict__ mi, float* __restrict__ aggx,
                       int* __restrict__ hase, int E, int ntiles) {
    extern __shared__ float sm[];
    float* s_w2  = sm;              // eW2^T  [128][128] swizzled
    float* s_cw  = sm + 16384;      // cW1^T  [128][128]
    float* s_iw  = sm + 32768;      // iW1^T  [64][128]
    float* s_a   = sm + 40960;      // acts   [128 edges][128] swizzled
    float* s_eij = sm + 57344;      // 128
    float* s_phi = sm + 57472;      // 128
    float* s_red = sm + 57600;      // 128

    const int tid = threadIdx.x;
    const int lane = tid & 31, wid = tid >> 5;
    const int wm = wid >> 2, wn = wid & 3;   // 4m x 4e warp grid
    const int g = lane >> 2, q = lane & 3;
    const int m0 = wm * 32;                  // MT=2 -> 32 m per warp
    const int e0w = wn * 32;                 // NT=4 -> 32 edges per warp

    stage_w_sw(s_w2, eW2, 7, tid, WTHREADS);
    stage_w_sw(s_cw, cW1, 7, tid, WTHREADS);
    stage_w_sw(s_iw, iW1, 6, tid, WTHREADS);

    // per-thread epilogue constants
    float c_b2[4], c_cb1[4], c_cw2[4], c_ib1[2], c_iw2[2];
#pragma unroll
    for (int mt = 0; mt < 2; mt++) {
        int m = m0 + mt * 16 + g;
        c_b2[mt * 2]  = eb2[m];  c_b2[mt * 2 + 1]  = eb2[m + 8];
        c_cb1[mt * 2] = cb1[m];  c_cb1[mt * 2 + 1] = cb1[m + 8];
        c_cw2[mt * 2] = cW2[m];  c_cw2[mt * 2 + 1] = cW2[m + 8];
    }
    {
        int m = wm * 16 + g;
        c_ib1[0] = ib1[m]; c_ib1[1] = ib1[m + 8];
        c_iw2[0] = iW2[m]; c_iw2[1] = iW2[m + 8];
    }
    const float ib2v = ib2[0];
    __syncthreads();

    for (int t = blockIdx.x; t < ntiles; t += gridDim.x) {
        const int ebase = t * 128;

        // ---- build t1 = silu(P[row]+Q[col]+ds*w256+ea*w257+b1) into s_a ----
        {
            const int e = tid >> 2, qtr = tid & 3;   // 4 threads per edge
            const int ee = ebase + e;
            int r = 0, c = 0; float ds = 0.f, ea = 0.f;
            if (ee < E) {
                r = ei[ee]; c = ei[E + ee];
                float dx = x[r * 3 + 0] - x[c * 3 + 0];
                float dy = x[r * 3 + 1] - x[c * 3 + 1];
                float dz = x[r * 3 + 2] - x[c * 3 + 2];
                ds = dx * dx + dy * dy + dz * dz;
                ea = eattr[ee];
            }
            const float4* pp = (const float4*)(P + (size_t)r * 128) + qtr * 8;
            const float4* pq = (const float4*)(Q + (size_t)c * 128) + qtr * 8;
            const float4* pb1 = (const float4*)eb1 + qtr * 8;
            const float4* pw6 = (const float4*)(eW1 + 256 * 128) + qtr * 8;
            const float4* pw7 = (const float4*)(eW1 + 257 * 128) + qtr * 8;
            float4* prow = (float4*)(s_a + e * 128);
            const int x7 = e & 7;
#pragma unroll
            for (int i = 0; i < 8; i++) {
                float4 a = pp[i], b = pq[i];
                float4 w1 = __ldg(pb1 + i), w6 = __ldg(pw6 + i), w7 = __ldg(pw7 + i);
                float4 o;
                o.x = f2tf(siluf(a.x + b.x + ds * w6.x + ea * w7.x + w1.x));
                o.y = f2tf(siluf(a.y + b.y + ds * w6.y + ea * w7.y + w1.y));
                o.z = f2tf(siluf(a.z + b.z + ds * w6.z + ea * w7.z + w1.z));
                o.w = f2tf(siluf(a.w + b.w + ds * w6.w + ea * w7.w + w1.w));
                prow[(qtr * 8 + i) ^ x7] = o;
            }
        }
        __syncthreads();

        // ---- GEMM2: m = silu(t1 @ eW2 + b2) ----
        {
            float acc[2][4][4];
#pragma unroll
            for (int a = 0; a < 2; a++)
#pragma unroll
                for (int b = 0; b < 4; b++)
#pragma unroll
                    for (int c = 0; c < 4; c++) acc[a][b][c] = 0.f;
            gemm_sw<2, 4>(s_w2, s_a, acc, m0, e0w, g, q);
            __syncthreads();   // all reads of t1 complete
            if (tid < 128) { s_phi[tid] = 0.f; s_red[tid] = 0.f; }
#pragma unroll
            for (int mt = 0; mt < 2; mt++)
#pragma unroll
                for (int nt = 0; nt < 4; nt++) {
                    int m = m0 + mt * 16 + g;
                    int e = e0w + nt * 8 + 2 * q;
                    int gA = (m >> 2), gB = ((m + 8) >> 2);
                    int b0 = e * 128, b1r = (e + 1) * 128;
                    int e7a = e & 7, e7b = (e + 1) & 7;
                    int ml = m & 3;
                    s_a[b0  + (((gA ^ e7a) << 2) | ml)] =
                        f2tf(siluf(acc[mt][nt][0] + c_b2[mt * 2]));
                    s_a[b1r + (((gA ^ e7b) << 2) | ml)] =
                        f2tf(siluf(acc[mt][nt][1] + c_b2[mt * 2]));
                    s_a[b0  + (((gB ^ e7a) << 2) | ml)] =
                        f2tf(siluf(acc[mt][nt][2] + c_b2[mt * 2 + 1]));
                    s_a[b1r + (((gB ^ e7b) << 2) | ml)] =
                        f2tf(siluf(acc[mt][nt][3] + c_b2[mt * 2 + 1]));
                }
        }
        __syncthreads();

        // ---- coord head: phi = silu(m @ cW1 + cb1) . cW2 ----
        {
            float acc[2][4][4];
#pragma unroll
            for (int a = 0; a < 2; a++)
#pragma unroll
                for (int b = 0; b < 4; b++)
#pragma unroll
                    for (int c = 0; c < 4; c++) acc[a][b][c] = 0.f;
            gemm_sw<2, 4>(s_cw, s_a, acc, m0, e0w, g, q);
#pragma unroll
            for (int nt = 0; nt < 4; nt++) {
                float p0 = 0.f, p1 = 0.f;
#pragma unroll
                for (int mt = 0; mt < 2; mt++) {
                    p0 += siluf(acc[mt][nt][0] + c_cb1[mt * 2]) * c_cw2[mt * 2];
                    p1 += siluf(acc[mt][nt][1] + c_cb1[mt * 2]) * c_cw2[mt * 2];
                    p0 += siluf(acc[mt][nt][2] + c_cb1[mt * 2 + 1]) * c_cw2[mt * 2 + 1];
                    p1 += siluf(acc[mt][nt][3] + c_cb1[mt * 2 + 1]) * c_cw2[mt * 2 + 1];
                }
#pragma unroll
                for (int off = 4; off <= 16; off <<= 1) {
                    p0 += __shfl_xor_sync(0xffffffffu, p0, off);
                    p1 += __shfl_xor_sync(0xffffffffu, p1, off);
                }
                if (g == 0) {
                    atomicAdd(&s_phi[e0w + nt * 8 + 2 * q], p0);
                    atomicAdd(&s_phi[e0w + nt * 8 + 2 * q + 1], p1);
                }
            }
        }

        // ---- inf head (M=64, MT=1): logit ----
        {
            float acc[1][4][4];
#pragma unroll
            for (int b = 0; b < 4; b++)
#pragma unroll
                for (int c = 0; c < 4; c++) acc[0][b][c] = 0.f;
            gemm_sw<1, 4>(s_iw, s_a, acc, wm * 16, e0w, g, q);
#pragma unroll
            for (int nt = 0; nt < 4; nt++) {
                float p0 = siluf(acc[0][nt][0] + c_ib1[0]) * c_iw2[0]
                         + siluf(acc[0][nt][2] + c_ib1[1]) * c_iw2[1];
                float p1 = siluf(acc[0][nt][1] + c_ib1[0]) * c_iw2[0]
                         + siluf(acc[0][nt][3] + c_ib1[1]) * c_iw2[1];
#pragma unroll
                for (int off = 4; off <= 16; off <<= 1) {
                    p0 += __shfl_xor_sync(0xffffffffu, p0, off);
                    p1 += __shfl_xor_sync(0xffffffffu, p1, off);
                }
                if (g == 0) {
                    atomicAdd(&s_red[e0w + nt * 8 + 2 * q], p0);
                    atomicAdd(&s_red[e0w + nt * 8 + 2 * q + 1], p1);
                }
            }
        }
        __syncthreads();

        // ---- e_ij + x_update scatter ----
        if (tid < 128) {
            const int e = tid, ee = ebase + e;
            float ev = sigmf(s_red[e] + ib2v);
            s_eij[e] = ev;
            if (ee < E) {
                int r = ei[ee], c = ei[E + ee];
                float dx = x[r * 3 + 0] - x[c * 3 + 0];
                float dy = x[r * 3 + 1] - x[c * 3 + 1];
                float dz = x[r * 3 + 2] - x[c * 3 + 2];
                float f = ev * s_phi[e];
                atomicAdd(&aggx[(size_t)r * 3 + 0], f * dx);
                atomicAdd(&aggx[(size_t)r * 3 + 1], f * dy);
                atomicAdd(&aggx[(size_t)r * 3 + 2], f * dz);
                hase[r] = 1;
            }
        }
        __syncthreads();

        // ---- mi scatter: mi[row] += e_ij * m  ----
        for (int idx = tid; idx < 128 * 32; idx += WTHREADS) {
            int e = idx >> 5, j4 = idx & 31;
            int ee = ebase + e;
            if (ee < E) {
                float ev = s_eij[e];
                float4 v = ((const float4*)(s_a + e * 128))[j4 ^ (e & 7)];
                float* dst = mi + (size_t)ei[ee] * 128 + j4 * 4;
                asm volatile("red.global.add.v4.f32 [%0], {%1,%2,%3,%4};"
                             :: "l"(dst), "f"(ev * v.x), "f"(ev * v.y),
                                "f"(ev * v.z), "f"(ev * v.w) : "memory");
            }
        }
        __syncthreads();  // protect s_a / s_eij before next tile overwrites
    }
}

// ============================================================================
// Node kernel, 512 threads: vel head, node MLP (K=256 two passes), outputs.
// ============================================================================
#define N_SMEM ((16896 * 3 + 640) * 4)

__global__ __launch_bounds__(WTHREADS, 1)
void egnn_node_kernel(const float* __restrict__ h, const float* __restrict__ x,
                      const float* __restrict__ vinit,
                      const float* __restrict__ nW1, const float* __restrict__ nb1,
                      const float* __restrict__ nW2, const float* __restrict__ nb2,
                      const float* __restrict__ vW1, const float* __restrict__ vb1,
                      const float* __restrict__ vW2,
                      const float* __restrict__ mi, const float* __restrict__ aggx,
                      const int* __restrict__ hase,
                      float* __restrict__ out, int N, float invNm1) {
    extern __shared__ float sm[];
    float* s_a = sm;
    float* s_t = sm + 16896;
    float* s_w = sm + 33792;
    float* sc  = sm + 50688;
    float* s_nb1 = sc;           float* s_nb2 = sc + 128;
    float* s_vb1 = sc + 256;     float* s_vW2 = sc + 384;
    float* s_vel = sc + 512;

    const int tid = threadIdx.x;
    const int lane = tid & 31, wid = tid >> 5;
    const int wm = wid >> 2, wn = wid & 3;   // 4m x 4n
    const int m0 = wm * 32, e0w = wn * 32;   // MT=2, NT=4
    const int g = lane >> 2, q = lane & 3;
    const int n0 = blockIdx.x * 128;

    if (tid < 128) {
        s_nb1[tid] = nb1[tid]; s_nb2[tid] = nb2[tid];
        s_vb1[tid] = vb1[tid]; s_vW2[tid] = vW2[tid];
        s_vel[tid] = 0.f;
    }

    for (int idx = tid; idx < 128 * 32; idx += WTHREADS) {
        int e = idx >> 5, k4 = idx & 31;
        int n = n0 + e; if (n >= N) n = N - 1;
        float4 v = ((const float4*)(h + (size_t)n * 128))[k4];
        v.x = f2tf(v.x); v.y = f2tf(v.y); v.z = f2tf(v.z); v.w = f2tf(v.w);
        ((float4*)(s_a + e * 132))[k4] = v;
    }
    stage_wT(s_w, vW1, 127, 7, 128, tid, WTHREADS);
    __syncthreads();

    // vel head
    {
        float acc[2][4][4];
#pragma unroll
        for (int a = 0; a < 2; a++)
#pragma unroll
            for (int b = 0; b < 4; b++)
#pragma unroll
                for (int c = 0; c < 4; c++) acc[a][b][c] = 0.f;
        gemm128<2, 4>(s_w, s_a, acc, m0, e0w, lane);
#pragma unroll
        for (int nt = 0; nt < 4; nt++) {
            float p0 = 0.f, p1 = 0.f;
#pragma unroll
            for (int mt = 0; mt < 2; mt++) {
                int m = m0 + mt * 16 + g;
                p0 += siluf(acc[mt][nt][0] + s_vb1[m]) * s_vW2[m];
                p1 += siluf(acc[mt][nt][1] + s_vb1[m]) * s_vW2[m];
                p0 += siluf(acc[mt][nt][2] + s_vb1[m + 8]) * s_vW2[m + 8];
                p1 += siluf(acc[mt][nt][3] + s_vb1[m + 8]) * s_vW2[m + 8];
            }
#pragma unroll
            for (int off = 4; off <= 16; off <<= 1) {
                p0 += __shfl_xor_sync(0xffffffffu, p0, off);
                p1 += __shfl_xor_sync(0xffffffffu, p1, off);
            }
            if (g == 0) {
                atomicAdd(&s_vel[e0w + nt * 8 + 2 * q], p0);
                atomicAdd(&s_vel[e0w + nt * 8 + 2 * q + 1], p1);
            }
        }
    }
    __syncthreads();

    // node layer 1 over [h | m_i]
    float accN[2][4][4];
#pragma unroll
    for (int a = 0; a < 2; a++)
#pragma unroll
        for (int b = 0; b < 4; b++)
#pragma unroll
            for (int c = 0; c < 4; c++) accN[a][b][c] = 0.f;

    stage_wT(s_w, nW1, 127, 7, 128, tid, WTHREADS);
    __syncthreads();
    gemm128<2, 4>(s_w, s_a, accN, m0, e0w, lane);
    __syncthreads();

    for (int idx = tid; idx < 128 * 32; idx += WTHREADS) {
        int e = idx >> 5, k4 = idx & 31;
        int n = n0 + e; if (n >= N) n = N - 1;
        float4 v = ((const float4*)(mi + (size_t)n * 128))[k4];
        v.x = f2tf(v.x); v.y = f2tf(v.y); v.z = f2tf(v.z); v.w = f2tf(v.w);
        ((float4*)(s_a + e * 132))[k4] = v;
    }
    stage_wT(s_w, nW1 + (size_t)128 * 128, 127, 7, 128, tid, WTHREADS);
    __syncthreads();
    gemm128<2, 4>(s_w, s_a, accN, m0, e0w, lane);

#pragma unroll
    for (int mt = 0; mt < 2; mt++)
#pragma unroll
        for (int nt = 0; nt < 4; nt++) {
            int m = m0 + mt * 16 + g;
            int e = e0w + nt * 8 + 2 * q;
            s_t[(e)     * 132 + m]     = f2tf(siluf(accN[mt][nt][0] + s_nb1[m]));
            s_t[(e + 1) * 132 + m]     = f2tf(siluf(accN[mt][nt][1] + s_nb1[m]));
            s_t[(e)     * 132 + m + 8] = f2tf(siluf(accN[mt][nt][2] + s_nb1[m + 8]));
            s_t[(e + 1) * 132 + m + 8] = f2tf(siluf(accN[mt][nt][3] + s_nb1[m + 8]));
        }
    __syncthreads();

    // node layer 2
    stage_wT(s_w, nW2, 127, 7, 128, tid, WTHREADS);
    __syncthreads();
    {
        float acc[2][4][4];
#pragma unroll
        for (int a = 0; a < 2; a++)
#pragma unroll
            for (int b = 0; b < 4; b++)
#pragma unroll
                for (int c = 0; c < 4; c++) acc[a][b][c] = 0.f;
        gemm128<2, 4>(s_w, s_t, acc, m0, e0w, lane);
#pragma unroll
        for (int mt = 0; mt < 2; mt++)
#pragma unroll
            for (int nt = 0; nt < 4; nt++) {
                int m = m0 + mt * 16 + g;
                int e = e0w + nt * 8 + 2 * q;
#pragma unroll
                for (int c = 0; c < 4; c++) {
                    int mm = m + ((c >> 1) ? 8 : 0);
                    int ee = e + (c & 1);
                    int n = n0 + ee;
                    if (n < N)
                        out[(size_t)n * 128 + mm] = acc[mt][nt][c] + s_nb2[mm];
                }
            }
    }

    if (tid < 128) {
        int n = n0 + tid;
        if (n < N) {
            float vs = s_vel[tid];
            float v0 = vinit[(size_t)n * 3 + 0] * vs;
            float v1 = vinit[(size_t)n * 3 + 1] * vs;
            float v2 = vinit[(size_t)n * 3 + 2] * vs;
            float* out_x = out + (size_t)N * 128;
            float* out_v = out_x + (size_t)N * 3;
            out_v[(size_t)n * 3 + 0] = v0;
            out_v[(size_t)n * 3 + 1] = v1;
            out_v[(size_t)n * 3 + 2] = v2;
            float x0 = x[(size_t)n * 3 + 0], x1 = x[(size_t)n * 3 + 1], x2 = x[(size_t)n * 3 + 2];
            if (hase[n]) {
                x0 += v0 + aggx[(size_t)n * 3 + 0] * invNm1;
                x1 += v1 + aggx[(size_t)n * 3 + 1] * invNm1;
                x2 += v2 + aggx[(size_t)n * 3 + 2] * invNm1;
            }
            out_x[(size_t)n * 3 + 0] = x0;
            out_x[(size_t)n * 3 + 1] = x1;
            out_x[(size_t)n * 3 + 2] = x2;
        }
    }
}

// ============================================================================
// Launch
// ============================================================================
extern "C" void kernel_launch(void* const* d_in, const int* in_sizes, int n_in,
                              void* d_out, int out_size) {
    const float* h     = (const float*)d_in[0];
    const float* x     = (const float*)d_in[1];
    const float* eattr = (const float*)d_in[2];
    const float* vinit = (const float*)d_in[3];
    const int*   ei    = (const int*)d_in[4];
    const float* eW1 = (const float*)d_in[5];
    const float* eb1 = (const float*)d_in[6];
    const float* eW2 = (const float*)d_in[7];
    const float* eb2 = (const float*)d_in[8];
    const float* cW1 = (const float*)d_in[9];
    const float* cb1 = (const float*)d_in[10];
    const float* cW2 = (const float*)d_in[11];
    const float* iW1 = (const float*)d_in[12];
    const float* ib1 = (const float*)d_in[13];
    const float* iW2 = (const float*)d_in[14];
    const float* ib2 = (const float*)d_in[15];
    const float* nW1 = (const float*)d_in[16];
    const float* nb1 = (const float*)d_in[17];
    const float* nW2 = (const float*)d_in[18];
    const float* nb2 = (const float*)d_in[19];
    const float* vW1 = (const float*)d_in[20];
    const float* vb1 = (const float*)d_in[21];
    const float* vW2 = (const float*)d_in[22];

    const int N = in_sizes[0] / 128;
    const int E = in_sizes[2];
    float* out = (float*)d_out;
    const float invNm1 = 1.0f / (float)(N - 1);

    void *p_mi, *p_ax, *p_he, *p_P, *p_Q;
    cudaGetSymbolAddress(&p_mi, g_mi);
    cudaGetSymbolAddress(&p_ax, g_aggx);
    cudaGetSymbolAddress(&p_he, g_hase);
    cudaGetSymbolAddress(&p_P, g_P);
    cudaGetSymbolAddress(&p_Q, g_Q);
    cudaMemsetAsync(p_mi, 0, (size_t)N * 128 * sizeof(float));
    cudaMemsetAsync(p_ax, 0, (size_t)N * 3 * sizeof(float));
    cudaMemsetAsync(p_he, 0, (size_t)N * sizeof(int));

    cudaFuncSetAttribute(egnn_pq_kernel,
                         cudaFuncAttributeMaxDynamicSharedMemorySize, PQ_SMEM);
    cudaFuncSetAttribute(egnn_edge_persist,
                         cudaFuncAttributeMaxDynamicSharedMemorySize, E_SMEM);
    cudaFuncSetAttribute(egnn_node_kernel,
                         cudaFuncAttributeMaxDynamicSharedMemorySize, N_SMEM);

    int nblocks = (N + 127) / 128;
    egnn_pq_kernel<<<nblocks, PQTHREADS, PQ_SMEM>>>(h, eW1, (float*)p_P, (float*)p_Q, N);

    int ntiles = (E + 127) / 128;
    egnn_edge_persist<<<EGRID, WTHREADS, E_SMEM>>>(
        x, eattr, ei, eW1, eb1, eW2, eb2, cW1, cb1, cW2,
        iW1, ib1, iW2, ib2,
        (const float*)p_P, (const float*)p_Q,
        (float*)p_mi, (float*)p_ax, (int*)p_he, E, ntiles);

    egnn_node_kernel<<<nblocks, WTHREADS, N_SMEM>>>(
        h, x, vinit, nW1, nb1, nW2, nb2, vW1, vb1, vW2,
        (const float*)p_mi, (const float*)p_ax, (const int*)p_he,
        out, N, invNm1);
}

// round 11
// speedup vs baseline: 5.6414x; 1.3148x over previous
#include <cuda_runtime.h>
#include <cuda_fp16.h>
#include <cstdint>

#define PQTHREADS 256
#define WTHREADS 512
#define MAXN 65536
#define STR 68          // half2 (uint32) stride per operand row

// Scratch (__device__ globals per allocation-free rule)
__device__ float g_mi[(size_t)MAXN * 128];
__device__ float g_aggx[(size_t)MAXN * 3];
__device__ int   g_hase[MAXN];
__device__ float g_P[(size_t)MAXN * 128];   // h @ eW1[0:128]
__device__ float g_Q[(size_t)MAXN * 128];   // h @ eW1[128:256]

__device__ __forceinline__ float siluf(float v) { return v / (1.0f + __expf(-v)); }
__device__ __forceinline__ float sigmf(float v) { return 1.0f / (1.0f + __expf(-v)); }

__device__ __forceinline__ uint32_t packh2(float a, float b) {
    __half2 h = __floats2half2_rn(a, b);
    return *reinterpret_cast<uint32_t*>(&h);
}

// fp16 MMA m16n8k16, fp32 accumulate. D layout == m16n8k8 (reused epilogues).
__device__ __forceinline__ void mma_f16(float (&d)[4], const uint32_t (&a)[4],
                                        uint32_t b0, uint32_t b1) {
    asm volatile(
        "mma.sync.aligned.m16n8k16.row.col.f32.f16.f16.f32 "
        "{%0,%1,%2,%3}, {%4,%5,%6,%7}, {%8,%9}, {%0,%1,%2,%3};"
        : "+f"(d[0]), "+f"(d[1]), "+f"(d[2]), "+f"(d[3])
        : "r"(a[0]), "r"(a[1]), "r"(a[2]), "r"(a[3]), "r"(b0), "r"(b1));
}

// Stage W^T (gmem row-major [K=128][M]) as half2 rows: sW[m*STR + k/2]
__device__ __forceinline__ void stage_wh(uint32_t* sW, const float* __restrict__ W,
                                         int M, int tid, int nthr) {
    const int tasks = M * 32;            // K/4 groups per m
    for (int id = tid; id < tasks; id += nthr) {
        int m = id % M;                  // coalesced gmem reads in m
        int kq = id / M;
        int k0 = kq * 4;
        float w0 = W[(size_t)(k0 + 0) * M + m];
        float w1 = W[(size_t)(k0 + 1) * M + m];
        float w2 = W[(size_t)(k0 + 2) * M + m];
        float w3 = W[(size_t)(k0 + 3) * M + m];
        uint2 v; v.x = packh2(w0, w1); v.y = packh2(w2, w3);
        *(uint2*)(sW + m * STR + kq * 2) = v;
    }
}

// K=128 fp16 GEMM: sW rows = output features (A, row-major), sB rows = edges (B, col)
template <int MT, int NT>
__device__ __forceinline__ void gemm_h(const uint32_t* __restrict__ sW,
                                       const uint32_t* __restrict__ sB,
                                       float (&acc)[MT][NT][4],
                                       int m0, int e0, int lane) {
    const int g = lane >> 2, q = lane & 3;
#pragma unroll
    for (int kc = 0; kc < 8; kc++) {
        const int kk2 = kc * 8;          // half2 index of k-chunk base
        uint32_t a[MT][4];
#pragma unroll
        for (int mt = 0; mt < MT; mt++) {
            int base = (m0 + mt * 16 + g) * STR + kk2 + q;
            a[mt][0] = sW[base];
            a[mt][1] = sW[base + 8 * STR];
            a[mt][2] = sW[base + 4];
            a[mt][3] = sW[base + 8 * STR + 4];
        }
#pragma unroll
        for (int nt = 0; nt < NT; nt++) {
            int bb = (e0 + nt * 8 + g) * STR + kk2 + q;
            uint32_t b0 = sB[bb];
            uint32_t b1 = sB[bb + 4];
#pragma unroll
            for (int mt = 0; mt < MT; mt++) mma_f16(acc[mt][nt], a[mt], b0, b1);
        }
    }
}

// ============================================================================
// PQ kernel: P = h @ eW1[0:128], Q = h @ eW1[128:256]   (256 threads)
// ============================================================================
#define PQ_SMEM (17408 * 4)

__global__ __launch_bounds__(PQTHREADS)
void egnn_pq_kernel(const float* __restrict__ h, const float* __restrict__ eW1,
                    float* __restrict__ P, float* __restrict__ Q, int N) {
    extern __shared__ uint32_t smu[];
    uint32_t* s_h = smu;                 // 128 x STR
    uint32_t* s_w = smu + 8704;

    const int tid = threadIdx.x;
    const int lane = tid & 31, wid = tid >> 5;
    const int wm = wid >> 2, wn = wid & 3;
    const int m0 = wm * 64, e0 = wn * 32;
    const int n0 = blockIdx.x * 128;

    for (int idx = tid; idx < 128 * 32; idx += PQTHREADS) {
        int e = idx >> 5, k4 = idx & 31;
        int n = n0 + e; if (n >= N) n = N - 1;
        float4 v = ((const float4*)(h + (size_t)n * 128))[k4];
        uint2 p; p.x = packh2(v.x, v.y); p.y = packh2(v.z, v.w);
        *(uint2*)(s_h + e * STR + k4 * 2) = p;
    }

    for (int half = 0; half < 2; half++) {
        __syncthreads();
        stage_wh(s_w, eW1 + (size_t)half * 128 * 128, 128, tid, PQTHREADS);
        __syncthreads();
        float acc[4][4][4];
#pragma unroll
        for (int a = 0; a < 4; a++)
#pragma unroll
            for (int b = 0; b < 4; b++)
#pragma unroll
                for (int c = 0; c < 4; c++) acc[a][b][c] = 0.f;
        gemm_h<4, 4>(s_w, s_h, acc, m0, e0, lane);

        float* out = half ? Q : P;
        const int g = lane >> 2, q = lane & 3;
#pragma unroll
        for (int mt = 0; mt < 4; mt++)
#pragma unroll
            for (int nt = 0; nt < 4; nt++) {
                int m = m0 + mt * 16 + g;
                int e = e0 + nt * 8 + 2 * q;
#pragma unroll
                for (int c = 0; c < 4; c++) {
                    int mm = m + ((c >> 1) ? 8 : 0);
                    int ee = e + (c & 1);
                    int n = n0 + ee;
                    if (n < N) out[(size_t)n * 128 + mm] = acc[mt][nt][c];
                }
            }
    }
}

// ============================================================================
// Persistent edge kernel, 512 threads, fp16 mma.sync, weights smem-resident.
// smem uint32: w2 8704 | cw 8704 | iw 4352 | act 8704 | eij/phi/red 384
// ============================================================================
#define E_SMEM (30848 * 4)
#define EGRID 148

__global__ __launch_bounds__(WTHREADS, 1)
void egnn_edge_persist(const float* __restrict__ x, const float* __restrict__ eattr,
                       const int* __restrict__ ei,
                       const float* __restrict__ eW1, const float* __restrict__ eb1,
                       const float* __restrict__ eW2, const float* __restrict__ eb2,
                       const float* __restrict__ cW1, const float* __restrict__ cb1,
                       const float* __restrict__ cW2,
                       const float* __restrict__ iW1, const float* __restrict__ ib1,
                       const float* __restrict__ iW2, const float* __restrict__ ib2,
                       const float* __restrict__ P, const float* __restrict__ Q,
                       float* __restrict__ mi, float* __restrict__ aggx,
                       int* __restrict__ hase, int E, int ntiles) {
    extern __shared__ uint32_t smu[];
    uint32_t* s_w2 = smu;                // eW2^T   [128][STR]
    uint32_t* s_cw = smu + 8704;         // cW1^T   [128][STR]
    uint32_t* s_iw = smu + 17408;        // iW1^T   [64][STR]
    uint32_t* s_a  = smu + 21760;        // acts    [128][STR]
    float* s_eij = (float*)(smu + 30464);
    float* s_phi = s_eij + 128;
    float* s_red = s_phi + 128;

    const int tid = threadIdx.x;
    const int lane = tid & 31, wid = tid >> 5;
    const int wm = wid >> 2, wn = wid & 3;   // 4m x 4e warp grid
    const int g = lane >> 2, q = lane & 3;
    const int m0 = wm * 32;                  // MT=2
    const int e0w = wn * 32;                 // NT=4

    stage_wh(s_w2, eW2, 128, tid, WTHREADS);
    stage_wh(s_cw, cW1, 128, tid, WTHREADS);
    stage_wh(s_iw, iW1, 64, tid, WTHREADS);

    // per-thread epilogue constants
    float c_b2[4], c_cb1[4], c_cw2[4], c_ib1[2], c_iw2[2];
#pragma unroll
    for (int mt = 0; mt < 2; mt++) {
        int m = m0 + mt * 16 + g;
        c_b2[mt * 2]  = eb2[m];  c_b2[mt * 2 + 1]  = eb2[m + 8];
        c_cb1[mt * 2] = cb1[m];  c_cb1[mt * 2 + 1] = cb1[m + 8];
        c_cw2[mt * 2] = cW2[m];  c_cw2[mt * 2 + 1] = cW2[m + 8];
    }
    {
        int m = wm * 16 + g;
        c_ib1[0] = ib1[m]; c_ib1[1] = ib1[m + 8];
        c_iw2[0] = iW2[m]; c_iw2[1] = iW2[m + 8];
    }
    const float ib2v = ib2[0];
    __syncthreads();

    for (int t = blockIdx.x; t < ntiles; t += gridDim.x) {
        const int ebase = t * 128;

        // ---- A: t1 = silu(P[row]+Q[col]+ds*w256+ea*w257+b1) into s_a (fp16) --
        {
            if (tid < 256) {
                if (tid < 128) s_phi[tid] = 0.f; else s_red[tid - 128] = 0.f;
            }
            const int e = tid >> 2, qtr = tid & 3;   // 4 threads per edge
            const int ee = ebase + e;
            int r = 0, c = 0; float ds = 0.f, ea = 0.f;
            if (ee < E) {
                r = ei[ee]; c = ei[E + ee];
                float dx = x[r * 3 + 0] - x[c * 3 + 0];
                float dy = x[r * 3 + 1] - x[c * 3 + 1];
                float dz = x[r * 3 + 2] - x[c * 3 + 2];
                ds = dx * dx + dy * dy + dz * dz;
                ea = eattr[ee];
            }
            const float4* pp = (const float4*)(P + (size_t)r * 128) + qtr * 8;
            const float4* pq = (const float4*)(Q + (size_t)c * 128) + qtr * 8;
            const float4* pb1 = (const float4*)eb1 + qtr * 8;
            const float4* pw6 = (const float4*)(eW1 + 256 * 128) + qtr * 8;
            const float4* pw7 = (const float4*)(eW1 + 257 * 128) + qtr * 8;
            uint32_t* prow = s_a + e * STR + qtr * 16;
#pragma unroll
            for (int i = 0; i < 8; i++) {
                float4 a = pp[i], b = pq[i];
                float4 w1 = __ldg(pb1 + i), w6 = __ldg(pw6 + i), w7 = __ldg(pw7 + i);
                float o0 = siluf(a.x + b.x + ds * w6.x + ea * w7.x + w1.x);
                float o1 = siluf(a.y + b.y + ds * w6.y + ea * w7.y + w1.y);
                float o2 = siluf(a.z + b.z + ds * w6.z + ea * w7.z + w1.z);
                float o3 = siluf(a.w + b.w + ds * w6.w + ea * w7.w + w1.w);
                uint2 v; v.x = packh2(o0, o1); v.y = packh2(o2, o3);
                *(uint2*)(prow + i * 2) = v;
            }
        }
        __syncthreads();

        // ---- B: GEMM2  m = silu(t1 @ eW2 + b2), write back into s_a ----
        {
            float acc[2][4][4];
#pragma unroll
            for (int a = 0; a < 2; a++)
#pragma unroll
                for (int b = 0; b < 4; b++)
#pragma unroll
                    for (int c = 0; c < 4; c++) acc[a][b][c] = 0.f;
            gemm_h<2, 4>(s_w2, s_a, acc, m0, e0w, lane);
            __syncthreads();   // all reads of t1 complete
            __half* ha = (__half*)s_a;
#pragma unroll
            for (int mt = 0; mt < 2; mt++)
#pragma unroll
                for (int nt = 0; nt < 4; nt++) {
                    int m = m0 + mt * 16 + g;
                    int e = e0w + nt * 8 + 2 * q;
                    ha[e * 136 + m]           = __float2half(siluf(acc[mt][nt][0] + c_b2[mt * 2]));
                    ha[(e + 1) * 136 + m]     = __float2half(siluf(acc[mt][nt][1] + c_b2[mt * 2]));
                    ha[e * 136 + m + 8]       = __float2half(siluf(acc[mt][nt][2] + c_b2[mt * 2 + 1]));
                    ha[(e + 1) * 136 + m + 8] = __float2half(siluf(acc[mt][nt][3] + c_b2[mt * 2 + 1]));
                }
        }
        __syncthreads();

        // ---- C: coord head: phi = silu(m @ cW1 + cb1) . cW2 ----
        {
            float acc[2][4][4];
#pragma unroll
            for (int a = 0; a < 2; a++)
#pragma unroll
                for (int b = 0; b < 4; b++)
#pragma unroll
                    for (int c = 0; c < 4; c++) acc[a][b][c] = 0.f;
            gemm_h<2, 4>(s_cw, s_a, acc, m0, e0w, lane);
#pragma unroll
            for (int nt = 0; nt < 4; nt++) {
                float p0 = 0.f, p1 = 0.f;
#pragma unroll
                for (int mt = 0; mt < 2; mt++) {
                    p0 += siluf(acc[mt][nt][0] + c_cb1[mt * 2]) * c_cw2[mt * 2];
                    p1 += siluf(acc[mt][nt][1] + c_cb1[mt * 2]) * c_cw2[mt * 2];
                    p0 += siluf(acc[mt][nt][2] + c_cb1[mt * 2 + 1]) * c_cw2[mt * 2 + 1];
                    p1 += siluf(acc[mt][nt][3] + c_cb1[mt * 2 + 1]) * c_cw2[mt * 2 + 1];
                }
#pragma unroll
                for (int off = 4; off <= 16; off <<= 1) {
                    p0 += __shfl_xor_sync(0xffffffffu, p0, off);
                    p1 += __shfl_xor_sync(0xffffffffu, p1, off);
                }
                if (g == 0) {
                    atomicAdd(&s_phi[e0w + nt * 8 + 2 * q], p0);
                    atomicAdd(&s_phi[e0w + nt * 8 + 2 * q + 1], p1);
                }
            }
        }

        // ---- D: inf head (M=64, MT=1): logit ----
        {
            float acc[1][4][4];
#pragma unroll
            for (int b = 0; b < 4; b++)
#pragma unroll
                for (int c = 0; c < 4; c++) acc[0][b][c] = 0.f;
            gemm_h<1, 4>(s_iw, s_a, acc, wm * 16, e0w, lane);
#pragma unroll
            for (int nt = 0; nt < 4; nt++) {
                float p0 = siluf(acc[0][nt][0] + c_ib1[0]) * c_iw2[0]
                         + siluf(acc[0][nt][2] + c_ib1[1]) * c_iw2[1];
                float p1 = siluf(acc[0][nt][1] + c_ib1[0]) * c_iw2[0]
                         + siluf(acc[0][nt][3] + c_ib1[1]) * c_iw2[1];
#pragma unroll
                for (int off = 4; off <= 16; off <<= 1) {
                    p0 += __shfl_xor_sync(0xffffffffu, p0, off);
                    p1 += __shfl_xor_sync(0xffffffffu, p1, off);
                }
                if (g == 0) {
                    atomicAdd(&s_red[e0w + nt * 8 + 2 * q], p0);
                    atomicAdd(&s_red[e0w + nt * 8 + 2 * q + 1], p1);
                }
            }
        }
        __syncthreads();

        // ---- E: e_ij + x_update scatter ----
        if (tid < 128) {
            const int e = tid, ee = ebase + e;
            float ev = sigmf(s_red[e] + ib2v);
            s_eij[e] = ev;
            if (ee < E) {
                int r = ei[ee], c = ei[E + ee];
                float dx = x[r * 3 + 0] - x[c * 3 + 0];
                float dy = x[r * 3 + 1] - x[c * 3 + 1];
                float dz = x[r * 3 + 2] - x[c * 3 + 2];
                float f = ev * s_phi[e];
                atomicAdd(&aggx[(size_t)r * 3 + 0], f * dx);
                atomicAdd(&aggx[(size_t)r * 3 + 1], f * dy);
                atomicAdd(&aggx[(size_t)r * 3 + 2], f * dz);
                hase[r] = 1;
            }
        }
        __syncthreads();

        // ---- F: mi scatter: mi[row] += e_ij * m ----
        for (int idx = tid; idx < 128 * 16; idx += WTHREADS) {
            int e = idx >> 4, j = idx & 15;
            int ee = ebase + e;
            if (ee < E) {
                float ev = s_eij[e];
                uint4 v = *(const uint4*)(s_a + e * STR + j * 4);
                float2 f0 = __half22float2(*(__half2*)&v.x);
                float2 f1 = __half22float2(*(__half2*)&v.y);
                float2 f2 = __half22float2(*(__half2*)&v.z);
                float2 f3 = __half22float2(*(__half2*)&v.w);
                float* dst = mi + (size_t)ei[ee] * 128 + j * 8;
                asm volatile("red.global.add.v4.f32 [%0], {%1,%2,%3,%4};"
                             :: "l"(dst), "f"(ev * f0.x), "f"(ev * f0.y),
                                "f"(ev * f1.x), "f"(ev * f1.y) : "memory");
                asm volatile("red.global.add.v4.f32 [%0], {%1,%2,%3,%4};"
                             :: "l"(dst + 4), "f"(ev * f2.x), "f"(ev * f2.y),
                                "f"(ev * f3.x), "f"(ev * f3.y) : "memory");
            }
        }
        __syncthreads();
    }
}

// ============================================================================
// Node kernel, 512 threads, fp16 mma.sync.
// smem uint32: s_a 8704 | s_t 8704 | s_w 8704 | consts 640
// ============================================================================
#define N_SMEM (26752 * 4)

__global__ __launch_bounds__(WTHREADS)
void egnn_node_kernel(const float* __restrict__ h, const float* __restrict__ x,
                      const float* __restrict__ vinit,
                      const float* __restrict__ nW1, const float* __restrict__ nb1,
                      const float* __restrict__ nW2, const float* __restrict__ nb2,
                      const float* __restrict__ vW1, const float* __restrict__ vb1,
                      const float* __restrict__ vW2,
                      const float* __restrict__ mi, const float* __restrict__ aggx,
                      const int* __restrict__ hase,
                      float* __restrict__ out, int N, float invNm1) {
    extern __shared__ uint32_t smu[];
    uint32_t* s_a = smu;
    uint32_t* s_t = smu + 8704;
    uint32_t* s_w = smu + 17408;
    float* sc  = (float*)(smu + 26112);
    float* s_nb1 = sc;           float* s_nb2 = sc + 128;
    float* s_vb1 = sc + 256;     float* s_vW2 = sc + 384;
    float* s_vel = sc + 512;

    const int tid = threadIdx.x;
    const int lane = tid & 31, wid = tid >> 5;
    const int wm = wid >> 2, wn = wid & 3;
    const int m0 = wm * 32, e0w = wn * 32;
    const int g = lane >> 2, q = lane & 3;
    const int n0 = blockIdx.x * 128;

    if (tid < 128) {
        s_nb1[tid] = nb1[tid]; s_nb2[tid] = nb2[tid];
        s_vb1[tid] = vb1[tid]; s_vW2[tid] = vW2[tid];
        s_vel[tid] = 0.f;
    }

    for (int idx = tid; idx < 128 * 32; idx += WTHREADS) {
        int e = idx >> 5, k4 = idx & 31;
        int n = n0 + e; if (n >= N) n = N - 1;
        float4 v = ((const float4*)(h + (size_t)n * 128))[k4];
        uint2 p; p.x = packh2(v.x, v.y); p.y = packh2(v.z, v.w);
        *(uint2*)(s_a + e * STR + k4 * 2) = p;
    }
    stage_wh(s_w, vW1, 128, tid, WTHREADS);
    __syncthreads();

    // vel head
    {
        float acc[2][4][4];
#pragma unroll
        for (int a = 0; a < 2; a++)
#pragma unroll
            for (int b = 0; b < 4; b++)
#pragma unroll
                for (int c = 0; c < 4; c++) acc[a][b][c] = 0.f;
        gemm_h<2, 4>(s_w, s_a, acc, m0, e0w, lane);
#pragma unroll
        for (int nt = 0; nt < 4; nt++) {
            float p0 = 0.f, p1 = 0.f;
#pragma unroll
            for (int mt = 0; mt < 2; mt++) {
                int m = m0 + mt * 16 + g;
                p0 += siluf(acc[mt][nt][0] + s_vb1[m]) * s_vW2[m];
                p1 += siluf(acc[mt][nt][1] + s_vb1[m]) * s_vW2[m];
                p0 += siluf(acc[mt][nt][2] + s_vb1[m + 8]) * s_vW2[m + 8];
                p1 += siluf(acc[mt][nt][3] + s_vb1[m + 8]) * s_vW2[m + 8];
            }
#pragma unroll
            for (int off = 4; off <= 16; off <<= 1) {
                p0 += __shfl_xor_sync(0xffffffffu, p0, off);
                p1 += __shfl_xor_sync(0xffffffffu, p1, off);
            }
            if (g == 0) {
                atomicAdd(&s_vel[e0w + nt * 8 + 2 * q], p0);
                atomicAdd(&s_vel[e0w + nt * 8 + 2 * q + 1], p1);
            }
        }
    }
    __syncthreads();

    // node layer 1 over [h | m_i] (two K=128 passes)
    float accN[2][4][4];
#pragma unroll
    for (int a = 0; a < 2; a++)
#pragma unroll
        for (int b = 0; b < 4; b++)
#pragma unroll
            for (int c = 0; c < 4; c++) accN[a][b][c] = 0.f;

    stage_wh(s_w, nW1, 128, tid, WTHREADS);
    __syncthreads();
    gemm_h<2, 4>(s_w, s_a, accN, m0, e0w, lane);
    __syncthreads();

    for (int idx = tid; idx < 128 * 32; idx += WTHREADS) {
        int e = idx >> 5, k4 = idx & 31;
        int n = n0 + e; if (n >= N) n = N - 1;
        float4 v = ((const float4*)(mi + (size_t)n * 128))[k4];
        uint2 p; p.x = packh2(v.x, v.y); p.y = packh2(v.z, v.w);
        *(uint2*)(s_a + e * STR + k4 * 2) = p;
    }
    stage_wh(s_w, nW1 + (size_t)128 * 128, 128, tid, WTHREADS);
    __syncthreads();
    gemm_h<2, 4>(s_w, s_a, accN, m0, e0w, lane);

    {
        __half* ht = (__half*)s_t;
#pragma unroll
        for (int mt = 0; mt < 2; mt++)
#pragma unroll
            for (int nt = 0; nt < 4; nt++) {
                int m = m0 + mt * 16 + g;
                int e = e0w + nt * 8 + 2 * q;
                ht[e * 136 + m]           = __float2half(siluf(accN[mt][nt][0] + s_nb1[m]));
                ht[(e + 1) * 136 + m]     = __float2half(siluf(accN[mt][nt][1] + s_nb1[m]));
                ht[e * 136 + m + 8]       = __float2half(siluf(accN[mt][nt][2] + s_nb1[m + 8]));
                ht[(e + 1) * 136 + m + 8] = __float2half(siluf(accN[mt][nt][3] + s_nb1[m + 8]));
            }
    }
    __syncthreads();

    // node layer 2
    stage_wh(s_w, nW2, 128, tid, WTHREADS);
    __syncthreads();
    {
        float acc[2][4][4];
#pragma unroll
        for (int a = 0; a < 2; a++)
#pragma unroll
            for (int b = 0; b < 4; b++)
#pragma unroll
                for (int c = 0; c < 4; c++) acc[a][b][c] = 0.f;
        gemm_h<2, 4>(s_w, s_t, acc, m0, e0w, lane);
#pragma unroll
        for (int mt = 0; mt < 2; mt++)
#pragma unroll
            for (int nt = 0; nt < 4; nt++) {
                int m = m0 + mt * 16 + g;
                int e = e0w + nt * 8 + 2 * q;
#pragma unroll
                for (int c = 0; c < 4; c++) {
                    int mm = m + ((c >> 1) ? 8 : 0);
                    int ee = e + (c & 1);
                    int n = n0 + ee;
                    if (n < N)
                        out[(size_t)n * 128 + mm] = acc[mt][nt][c] + s_nb2[mm];
                }
            }
    }

    if (tid < 128) {
        int n = n0 + tid;
        if (n < N) {
            float vs = s_vel[tid];
            float v0 = vinit[(size_t)n * 3 + 0] * vs;
            float v1 = vinit[(size_t)n * 3 + 1] * vs;
            float v2 = vinit[(size_t)n * 3 + 2] * vs;
            float* out_x = out + (size_t)N * 128;
            float* out_v = out_x + (size_t)N * 3;
            out_v[(size_t)n * 3 + 0] = v0;
            out_v[(size_t)n * 3 + 1] = v1;
            out_v[(size_t)n * 3 + 2] = v2;
            float x0 = x[(size_t)n * 3 + 0], x1 = x[(size_t)n * 3 + 1], x2 = x[(size_t)n * 3 + 2];
            if (hase[n]) {
                x0 += v0 + aggx[(size_t)n * 3 + 0] * invNm1;
                x1 += v1 + aggx[(size_t)n * 3 + 1] * invNm1;
                x2 += v2 + aggx[(size_t)n * 3 + 2] * invNm1;
            }
            out_x[(size_t)n * 3 + 0] = x0;
            out_x[(size_t)n * 3 + 1] = x1;
            out_x[(size_t)n * 3 + 2] = x2;
        }
    }
}

// ============================================================================
// Launch
// ============================================================================
extern "C" void kernel_launch(void* const* d_in, const int* in_sizes, int n_in,
                              void* d_out, int out_size) {
    const float* h     = (const float*)d_in[0];
    const float* x     = (const float*)d_in[1];
    const float* eattr = (const float*)d_in[2];
    const float* vinit = (const float*)d_in[3];
    const int*   ei    = (const int*)d_in[4];
    const float* eW1 = (const float*)d_in[5];
    const float* eb1 = (const float*)d_in[6];
    const float* eW2 = (const float*)d_in[7];
    const float* eb2 = (const float*)d_in[8];
    const float* cW1 = (const float*)d_in[9];
    const float* cb1 = (const float*)d_in[10];
    const float* cW2 = (const float*)d_in[11];
    const float* iW1 = (const float*)d_in[12];
    const float* ib1 = (const float*)d_in[13];
    const float* iW2 = (const float*)d_in[14];
    const float* ib2 = (const float*)d_in[15];
    const float* nW1 = (const float*)d_in[16];
    const float* nb1 = (const float*)d_in[17];
    const float* nW2 = (const float*)d_in[18];
    const float* nb2 = (const float*)d_in[19];
    const float* vW1 = (const float*)d_in[20];
    const float* vb1 = (const float*)d_in[21];
    const float* vW2 = (const float*)d_in[22];

    const int N = in_sizes[0] / 128;
    const int E = in_sizes[2];
    float* out = (float*)d_out;
    const float invNm1 = 1.0f / (float)(N - 1);

    void *p_mi, *p_ax, *p_he, *p_P, *p_Q;
    cudaGetSymbolAddress(&p_mi, g_mi);
    cudaGetSymbolAddress(&p_ax, g_aggx);
    cudaGetSymbolAddress(&p_he, g_hase);
    cudaGetSymbolAddress(&p_P, g_P);
    cudaGetSymbolAddress(&p_Q, g_Q);
    cudaMemsetAsync(p_mi, 0, (size_t)N * 128 * sizeof(float));
    cudaMemsetAsync(p_ax, 0, (size_t)N * 3 * sizeof(float));
    cudaMemsetAsync(p_he, 0, (size_t)N * sizeof(int));

    cudaFuncSetAttribute(egnn_pq_kernel,
                         cudaFuncAttributeMaxDynamicSharedMemorySize, PQ_SMEM);
    cudaFuncSetAttribute(egnn_edge_persist,
                         cudaFuncAttributeMaxDynamicSharedMemorySize, E_SMEM);
    cudaFuncSetAttribute(egnn_node_kernel,
                         cudaFuncAttributeMaxDynamicSharedMemorySize, N_SMEM);

    int nblocks = (N + 127) / 128;
    egnn_pq_kernel<<<nblocks, PQTHREADS, PQ_SMEM>>>(h, eW1, (float*)p_P, (float*)p_Q, N);

    int ntiles = (E + 127) / 128;
    egnn_edge_persist<<<EGRID, WTHREADS, E_SMEM>>>(
        x, eattr, ei, eW1, eb1, eW2, eb2, cW1, cb1, cW2,
        iW1, ib1, iW2, ib2,
        (const float*)p_P, (const float*)p_Q,
        (float*)p_mi, (float*)p_ax, (int*)p_he, E, ntiles);

    egnn_node_kernel<<<nblocks, WTHREADS, N_SMEM>>>(
        h, x, vinit, nW1, nb1, nW2, nb2, vW1, vb1, vW2,
        (const float*)p_mi, (const float*)p_ax, (const int*)p_he,
        out, N, invNm1);
}

// round 12
// speedup vs baseline: 6.7020x; 1.1880x over previous
#include <cuda_runtime.h>
#include <cuda_fp16.h>
#include <cstdint>

#define PQTHREADS 256
#define WTHREADS 512
#define MAXN 65536
#define STR 68          // half2 (uint32) stride per operand row

// Scratch (__device__ globals per allocation-free rule)
__device__ float g_mi[(size_t)MAXN * 128];
__device__ float g_aggx[(size_t)MAXN * 3];
__device__ int   g_hase[MAXN];
__device__ float g_P[(size_t)MAXN * 128];   // h @ eW1[0:128]
__device__ float g_Q[(size_t)MAXN * 128];   // h @ eW1[128:256]

__device__ __forceinline__ float siluf(float v) { return v / (1.0f + __expf(-v)); }
__device__ __forceinline__ float sigmf(float v) { return 1.0f / (1.0f + __expf(-v)); }

__device__ __forceinline__ uint32_t packh2(float a, float b) {
    __half2 h = __floats2half2_rn(a, b);
    return *reinterpret_cast<uint32_t*>(&h);
}

// fp16 MMA m16n8k16, fp32 accumulate.
__device__ __forceinline__ void mma_f16(float (&d)[4], const uint32_t (&a)[4],
                                        uint32_t b0, uint32_t b1) {
    asm volatile(
        "mma.sync.aligned.m16n8k16.row.col.f32.f16.f16.f32 "
        "{%0,%1,%2,%3}, {%4,%5,%6,%7}, {%8,%9}, {%0,%1,%2,%3};"
        : "+f"(d[0]), "+f"(d[1]), "+f"(d[2]), "+f"(d[3])
        : "r"(a[0]), "r"(a[1]), "r"(a[2]), "r"(a[3]), "r"(b0), "r"(b1));
}

// Stage W^T (gmem row-major [K=128][M]) as half2 rows: sW[m*STR + k/2]
__device__ __forceinline__ void stage_wh(uint32_t* sW, const float* __restrict__ W,
                                         int M, int tid, int nthr) {
    const int tasks = M * 32;            // K/4 groups per m
    for (int id = tid; id < tasks; id += nthr) {
        int m = id % M;                  // coalesced gmem reads in m
        int kq = id / M;
        int k0 = kq * 4;
        float w0 = W[(size_t)(k0 + 0) * M + m];
        float w1 = W[(size_t)(k0 + 1) * M + m];
        float w2 = W[(size_t)(k0 + 2) * M + m];
        float w3 = W[(size_t)(k0 + 3) * M + m];
        uint2 v; v.x = packh2(w0, w1); v.y = packh2(w2, w3);
        *(uint2*)(sW + m * STR + kq * 2) = v;
    }
}

// K=128 fp16 GEMM: sW rows = output features (A), sB rows = edges (B)
template <int MT, int NT>
__device__ __forceinline__ void gemm_h(const uint32_t* __restrict__ sW,
                                       const uint32_t* __restrict__ sB,
                                       float (&acc)[MT][NT][4],
                                       int m0, int e0, int lane) {
    const int g = lane >> 2, q = lane & 3;
#pragma unroll
    for (int kc = 0; kc < 8; kc++) {
        const int kk2 = kc * 8;
        uint32_t a[MT][4];
#pragma unroll
        for (int mt = 0; mt < MT; mt++) {
            int base = (m0 + mt * 16 + g) * STR + kk2 + q;
            a[mt][0] = sW[base];
            a[mt][1] = sW[base + 8 * STR];
            a[mt][2] = sW[base + 4];
            a[mt][3] = sW[base + 8 * STR + 4];
        }
#pragma unroll
        for (int nt = 0; nt < NT; nt++) {
            int bb = (e0 + nt * 8 + g) * STR + kk2 + q;
            uint32_t b0 = sB[bb];
            uint32_t b1 = sB[bb + 4];
#pragma unroll
            for (int mt = 0; mt < MT; mt++) mma_f16(acc[mt][nt], a[mt], b0, b1);
        }
    }
}

// ============================================================================
// PQ kernel: P = h @ eW1[0:128], Q = h @ eW1[128:256]   (256 threads)
// ============================================================================
#define PQ_SMEM (17408 * 4)

__global__ __launch_bounds__(PQTHREADS)
void egnn_pq_kernel(const float* __restrict__ h, const float* __restrict__ eW1,
                    float* __restrict__ P, float* __restrict__ Q, int N) {
    extern __shared__ uint32_t smu[];
    uint32_t* s_h = smu;                 // 128 x STR
    uint32_t* s_w = smu + 8704;

    const int tid = threadIdx.x;
    const int lane = tid & 31, wid = tid >> 5;
    const int wm = wid >> 2, wn = wid & 3;
    const int m0 = wm * 64, e0 = wn * 32;
    const int n0 = blockIdx.x * 128;

    for (int idx = tid; idx < 128 * 32; idx += PQTHREADS) {
        int e = idx >> 5, k4 = idx & 31;
        int n = n0 + e; if (n >= N) n = N - 1;
        float4 v = ((const float4*)(h + (size_t)n * 128))[k4];
        uint2 p; p.x = packh2(v.x, v.y); p.y = packh2(v.z, v.w);
        *(uint2*)(s_h + e * STR + k4 * 2) = p;
    }

    for (int half = 0; half < 2; half++) {
        __syncthreads();
        stage_wh(s_w, eW1 + (size_t)half * 128 * 128, 128, tid, PQTHREADS);
        __syncthreads();
        float acc[4][4][4];
#pragma unroll
        for (int a = 0; a < 4; a++)
#pragma unroll
            for (int b = 0; b < 4; b++)
#pragma unroll
                for (int c = 0; c < 4; c++) acc[a][b][c] = 0.f;
        gemm_h<4, 4>(s_w, s_h, acc, m0, e0, lane);

        float* out = half ? Q : P;
        const int g = lane >> 2, q = lane & 3;
#pragma unroll
        for (int mt = 0; mt < 4; mt++)
#pragma unroll
            for (int nt = 0; nt < 4; nt++) {
                int m = m0 + mt * 16 + g;
                int e = e0 + nt * 8 + 2 * q;
#pragma unroll
                for (int c = 0; c < 4; c++) {
                    int mm = m + ((c >> 1) ? 8 : 0);
                    int ee = e + (c & 1);
                    int n = n0 + ee;
                    if (n < N) out[(size_t)n * 128 + mm] = acc[mt][nt][c];
                }
            }
    }
}

// ============================================================================
// Persistent edge kernel, 64-edge tiles, 512 threads, 2 CTAs/SM.
// Warp grid 4m x 4e: MT=2 (32 rows/warp), NT=2 (16 edges/warp).
// smem uint32: w2 8704 | cw 8704 | iw 4352 | act 4352 | eij/phi/red 192
// total 26304 u32 = 105,216 B  (x2 CTAs = 210 KB < 228 KB)
// ============================================================================
#define E_SMEM (26304 * 4)
#define EGRID 296
#define ETILE 64

__global__ __launch_bounds__(WTHREADS, 2)
void egnn_edge_persist(const float* __restrict__ x, const float* __restrict__ eattr,
                       const int* __restrict__ ei,
                       const float* __restrict__ eW1, const float* __restrict__ eb1,
                       const float* __restrict__ eW2, const float* __restrict__ eb2,
                       const float* __restrict__ cW1, const float* __restrict__ cb1,
                       const float* __restrict__ cW2,
                       const float* __restrict__ iW1, const float* __restrict__ ib1,
                       const float* __restrict__ iW2, const float* __restrict__ ib2,
                       const float* __restrict__ P, const float* __restrict__ Q,
                       float* __restrict__ mi, float* __restrict__ aggx,
                       int* __restrict__ hase, int E, int ntiles) {
    extern __shared__ uint32_t smu[];
    uint32_t* s_w2 = smu;                // eW2^T   [128][STR]
    uint32_t* s_cw = smu + 8704;         // cW1^T   [128][STR]
    uint32_t* s_iw = smu + 17408;        // iW1^T   [64][STR]
    uint32_t* s_a  = smu + 21760;        // acts    [64][STR]
    float* s_eij = (float*)(smu + 26112);   // 64
    float* s_phi = s_eij + 64;              // 64
    float* s_red = s_phi + 64;              // 64

    const int tid = threadIdx.x;
    const int lane = tid & 31, wid = tid >> 5;
    const int wm = wid >> 2, wn = wid & 3;   // 4m x 4e
    const int g = lane >> 2, q = lane & 3;
    const int m0 = wm * 32;                  // MT=2
    const int e0w = wn * 16;                 // NT=2

    stage_wh(s_w2, eW2, 128, tid, WTHREADS);
    stage_wh(s_cw, cW1, 128, tid, WTHREADS);
    stage_wh(s_iw, iW1, 64, tid, WTHREADS);

    // per-thread epilogue constants
    float c_b2[4], c_cb1[4], c_cw2[4], c_ib1[2], c_iw2[2];
#pragma unroll
    for (int mt = 0; mt < 2; mt++) {
        int m = m0 + mt * 16 + g;
        c_b2[mt * 2]  = eb2[m];  c_b2[mt * 2 + 1]  = eb2[m + 8];
        c_cb1[mt * 2] = cb1[m];  c_cb1[mt * 2 + 1] = cb1[m + 8];
        c_cw2[mt * 2] = cW2[m];  c_cw2[mt * 2 + 1] = cW2[m + 8];
    }
    {
        int m = wm * 16 + g;
        c_ib1[0] = ib1[m]; c_ib1[1] = ib1[m + 8];
        c_iw2[0] = iW2[m]; c_iw2[1] = iW2[m + 8];
    }
    const float ib2v = ib2[0];
    __syncthreads();

    for (int t = blockIdx.x; t < ntiles; t += gridDim.x) {
        const int ebase = t * ETILE;

        // ---- A: t1 = silu(P[row]+Q[col]+ds*w256+ea*w257+b1) into s_a (fp16) --
        {
            if (tid < 128) {
                if (tid < 64) s_phi[tid] = 0.f; else s_red[tid - 64] = 0.f;
            }
            const int e = tid >> 3, qtr = tid & 7;   // 8 threads per edge
            const int ee = ebase + e;
            int r = 0, c = 0; float ds = 0.f, ea = 0.f;
            if (ee < E) {
                r = ei[ee]; c = ei[E + ee];
                float dx = x[r * 3 + 0] - x[c * 3 + 0];
                float dy = x[r * 3 + 1] - x[c * 3 + 1];
                float dz = x[r * 3 + 2] - x[c * 3 + 2];
                ds = dx * dx + dy * dy + dz * dz;
                ea = eattr[ee];
            }
            const float4* pp = (const float4*)(P + (size_t)r * 128) + qtr * 4;
            const float4* pq = (const float4*)(Q + (size_t)c * 128) + qtr * 4;
            const float4* pb1 = (const float4*)eb1 + qtr * 4;
            const float4* pw6 = (const float4*)(eW1 + 256 * 128) + qtr * 4;
            const float4* pw7 = (const float4*)(eW1 + 257 * 128) + qtr * 4;
            uint32_t* prow = s_a + e * STR + qtr * 8;
#pragma unroll
            for (int i = 0; i < 4; i++) {
                float4 a = pp[i], b = pq[i];
                float4 w1 = __ldg(pb1 + i), w6 = __ldg(pw6 + i), w7 = __ldg(pw7 + i);
                float o0 = siluf(a.x + b.x + ds * w6.x + ea * w7.x + w1.x);
                float o1 = siluf(a.y + b.y + ds * w6.y + ea * w7.y + w1.y);
                float o2 = siluf(a.z + b.z + ds * w6.z + ea * w7.z + w1.z);
                float o3 = siluf(a.w + b.w + ds * w6.w + ea * w7.w + w1.w);
                uint2 v; v.x = packh2(o0, o1); v.y = packh2(o2, o3);
                *(uint2*)(prow + i * 2) = v;
            }
        }
        __syncthreads();

        // ---- B: GEMM2  m = silu(t1 @ eW2 + b2), write back into s_a ----
        {
            float acc[2][2][4];
#pragma unroll
            for (int a = 0; a < 2; a++)
#pragma unroll
                for (int b = 0; b < 2; b++)
#pragma unroll
                    for (int c = 0; c < 4; c++) acc[a][b][c] = 0.f;
            gemm_h<2, 2>(s_w2, s_a, acc, m0, e0w, lane);
            __syncthreads();   // all reads of t1 complete
            __half* ha = (__half*)s_a;
#pragma unroll
            for (int mt = 0; mt < 2; mt++)
#pragma unroll
                for (int nt = 0; nt < 2; nt++) {
                    int m = m0 + mt * 16 + g;
                    int e = e0w + nt * 8 + 2 * q;
                    ha[e * 136 + m]           = __float2half(siluf(acc[mt][nt][0] + c_b2[mt * 2]));
                    ha[(e + 1) * 136 + m]     = __float2half(siluf(acc[mt][nt][1] + c_b2[mt * 2]));
                    ha[e * 136 + m + 8]       = __float2half(siluf(acc[mt][nt][2] + c_b2[mt * 2 + 1]));
                    ha[(e + 1) * 136 + m + 8] = __float2half(siluf(acc[mt][nt][3] + c_b2[mt * 2 + 1]));
                }
        }
        __syncthreads();

        // ---- C: coord head: phi = silu(m @ cW1 + cb1) . cW2 ----
        {
            float acc[2][2][4];
#pragma unroll
            for (int a = 0; a < 2; a++)
#pragma unroll
                for (int b = 0; b < 2; b++)
#pragma unroll
                    for (int c = 0; c < 4; c++) acc[a][b][c] = 0.f;
            gemm_h<2, 2>(s_cw, s_a, acc, m0, e0w, lane);
#pragma unroll
            for (int nt = 0; nt < 2; nt++) {
                float p0 = 0.f, p1 = 0.f;
#pragma unroll
                for (int mt = 0; mt < 2; mt++) {
                    p0 += siluf(acc[mt][nt][0] + c_cb1[mt * 2]) * c_cw2[mt * 2];
                    p1 += siluf(acc[mt][nt][1] + c_cb1[mt * 2]) * c_cw2[mt * 2];
                    p0 += siluf(acc[mt][nt][2] + c_cb1[mt * 2 + 1]) * c_cw2[mt * 2 + 1];
                    p1 += siluf(acc[mt][nt][3] + c_cb1[mt * 2 + 1]) * c_cw2[mt * 2 + 1];
                }
#pragma unroll
                for (int off = 4; off <= 16; off <<= 1) {
                    p0 += __shfl_xor_sync(0xffffffffu, p0, off);
                    p1 += __shfl_xor_sync(0xffffffffu, p1, off);
                }
                if (g == 0) {
                    atomicAdd(&s_phi[e0w + nt * 8 + 2 * q], p0);
                    atomicAdd(&s_phi[e0w + nt * 8 + 2 * q + 1], p1);
                }
            }
        }

        // ---- D: inf head (M=64, MT=1): logit ----
        {
            float acc[1][2][4];
#pragma unroll
            for (int b = 0; b < 2; b++)
#pragma unroll
                for (int c = 0; c < 4; c++) acc[0][b][c] = 0.f;
            gemm_h<1, 2>(s_iw, s_a, acc, wm * 16, e0w, lane);
#pragma unroll
            for (int nt = 0; nt < 2; nt++) {
                float p0 = siluf(acc[0][nt][0] + c_ib1[0]) * c_iw2[0]
                         + siluf(acc[0][nt][2] + c_ib1[1]) * c_iw2[1];
                float p1 = siluf(acc[0][nt][1] + c_ib1[0]) * c_iw2[0]
                         + siluf(acc[0][nt][3] + c_ib1[1]) * c_iw2[1];
#pragma unroll
                for (int off = 4; off <= 16; off <<= 1) {
                    p0 += __shfl_xor_sync(0xffffffffu, p0, off);
                    p1 += __shfl_xor_sync(0xffffffffu, p1, off);
                }
                if (g == 0) {
                    atomicAdd(&s_red[e0w + nt * 8 + 2 * q], p0);
                    atomicAdd(&s_red[e0w + nt * 8 + 2 * q + 1], p1);
                }
            }
        }
        __syncthreads();

        // ---- E: e_ij + x_update scatter ----
        if (tid < ETILE) {
            const int e = tid, ee = ebase + e;
            float ev = sigmf(s_red[e] + ib2v);
            s_eij[e] = ev;
            if (ee < E) {
                int r = ei[ee], c = ei[E + ee];
                float dx = x[r * 3 + 0] - x[c * 3 + 0];
                float dy = x[r * 3 + 1] - x[c * 3 + 1];
                float dz = x[r * 3 + 2] - x[c * 3 + 2];
                float f = ev * s_phi[e];
                atomicAdd(&aggx[(size_t)r * 3 + 0], f * dx);
                atomicAdd(&aggx[(size_t)r * 3 + 1], f * dy);
                atomicAdd(&aggx[(size_t)r * 3 + 2], f * dz);
                hase[r] = 1;
            }
        }
        __syncthreads();

        // ---- F: mi scatter: mi[row] += e_ij * m ----
        for (int idx = tid; idx < ETILE * 16; idx += WTHREADS) {
            int e = idx >> 4, j = idx & 15;
            int ee = ebase + e;
            if (ee < E) {
                float ev = s_eij[e];
                uint4 v = *(const uint4*)(s_a + e * STR + j * 4);
                float2 f0 = __half22float2(*(__half2*)&v.x);
                float2 f1 = __half22float2(*(__half2*)&v.y);
                float2 f2 = __half22float2(*(__half2*)&v.z);
                float2 f3 = __half22float2(*(__half2*)&v.w);
                float* dst = mi + (size_t)ei[ee] * 128 + j * 8;
                asm volatile("red.global.add.v4.f32 [%0], {%1,%2,%3,%4};"
                             :: "l"(dst), "f"(ev * f0.x), "f"(ev * f0.y),
                                "f"(ev * f1.x), "f"(ev * f1.y) : "memory");
                asm volatile("red.global.add.v4.f32 [%0], {%1,%2,%3,%4};"
                             :: "l"(dst + 4), "f"(ev * f2.x), "f"(ev * f2.y),
                                "f"(ev * f3.x), "f"(ev * f3.y) : "memory");
            }
        }
        __syncthreads();
    }
}

// ============================================================================
// Node kernel, 512 threads, 2 CTAs/SM (regs capped), fp16 mma.sync.
// smem uint32: s_a 8704 | s_t 8704 | s_w 8704 | consts 640
// ============================================================================
#define N_SMEM (26752 * 4)

__global__ __launch_bounds__(WTHREADS, 2)
void egnn_node_kernel(const float* __restrict__ h, const float* __restrict__ x,
                      const float* __restrict__ vinit,
                      const float* __restrict__ nW1, const float* __restrict__ nb1,
                      const float* __restrict__ nW2, const float* __restrict__ nb2,
                      const float* __restrict__ vW1, const float* __restrict__ vb1,
                      const float* __restrict__ vW2,
                      const float* __restrict__ mi, const float* __restrict__ aggx,
                      const int* __restrict__ hase,
                      float* __restrict__ out, int N, float invNm1) {
    extern __shared__ uint32_t smu[];
    uint32_t* s_a = smu;
    uint32_t* s_t = smu + 8704;
    uint32_t* s_w = smu + 17408;
    float* sc  = (float*)(smu + 26112);
    float* s_nb1 = sc;           float* s_nb2 = sc + 128;
    float* s_vb1 = sc + 256;     float* s_vW2 = sc + 384;
    float* s_vel = sc + 512;

    const int tid = threadIdx.x;
    const int lane = tid & 31, wid = tid >> 5;
    const int wm = wid >> 2, wn = wid & 3;
    const int m0 = wm * 32, e0w = wn * 32;
    const int g = lane >> 2, q = lane & 3;
    const int n0 = blockIdx.x * 128;

    if (tid < 128) {
        s_nb1[tid] = nb1[tid]; s_nb2[tid] = nb2[tid];
        s_vb1[tid] = vb1[tid]; s_vW2[tid] = vW2[tid];
        s_vel[tid] = 0.f;
    }

    for (int idx = tid; idx < 128 * 32; idx += WTHREADS) {
        int e = idx >> 5, k4 = idx & 31;
        int n = n0 + e; if (n >= N) n = N - 1;
        float4 v = ((const float4*)(h + (size_t)n * 128))[k4];
        uint2 p; p.x = packh2(v.x, v.y); p.y = packh2(v.z, v.w);
        *(uint2*)(s_a + e * STR + k4 * 2) = p;
    }
    stage_wh(s_w, vW1, 128, tid, WTHREADS);
    __syncthreads();

    // vel head
    {
        float acc[2][4][4];
#pragma unroll
        for (int a = 0; a < 2; a++)
#pragma unroll
            for (int b = 0; b < 4; b++)
#pragma unroll
                for (int c = 0; c < 4; c++) acc[a][b][c] = 0.f;
        gemm_h<2, 4>(s_w, s_a, acc, m0, e0w, lane);
#pragma unroll
        for (int nt = 0; nt < 4; nt++) {
            float p0 = 0.f, p1 = 0.f;
#pragma unroll
            for (int mt = 0; mt < 2; mt++) {
                int m = m0 + mt * 16 + g;
                p0 += siluf(acc[mt][nt][0] + s_vb1[m]) * s_vW2[m];
                p1 += siluf(acc[mt][nt][1] + s_vb1[m]) * s_vW2[m];
                p0 += siluf(acc[mt][nt][2] + s_vb1[m + 8]) * s_vW2[m + 8];
                p1 += siluf(acc[mt][nt][3] + s_vb1[m + 8]) * s_vW2[m + 8];
            }
#pragma unroll
            for (int off = 4; off <= 16; off <<= 1) {
                p0 += __shfl_xor_sync(0xffffffffu, p0, off);
                p1 += __shfl_xor_sync(0xffffffffu, p1, off);
            }
            if (g == 0) {
                atomicAdd(&s_vel[e0w + nt * 8 + 2 * q], p0);
                atomicAdd(&s_vel[e0w + nt * 8 + 2 * q + 1], p1);
            }
        }
    }
    __syncthreads();

    // node layer 1 over [h | m_i] (two K=128 passes)
    float accN[2][4][4];
#pragma unroll
    for (int a = 0; a < 2; a++)
#pragma unroll
        for (int b = 0; b < 4; b++)
#pragma unroll
            for (int c = 0; c < 4; c++) accN[a][b][c] = 0.f;

    stage_wh(s_w, nW1, 128, tid, WTHREADS);
    __syncthreads();
    gemm_h<2, 4>(s_w, s_a, accN, m0, e0w, lane);
    __syncthreads();

    for (int idx = tid; idx < 128 * 32; idx += WTHREADS) {
        int e = idx >> 5, k4 = idx & 31;
        int n = n0 + e; if (n >= N) n = N - 1;
        float4 v = ((const float4*)(mi + (size_t)n * 128))[k4];
        uint2 p; p.x = packh2(v.x, v.y); p.y = packh2(v.z, v.w);
        *(uint2*)(s_a + e * STR + k4 * 2) = p;
    }
    stage_wh(s_w, nW1 + (size_t)128 * 128, 128, tid, WTHREADS);
    __syncthreads();
    gemm_h<2, 4>(s_w, s_a, accN, m0, e0w, lane);

    {
        __half* ht = (__half*)s_t;
#pragma unroll
        for (int mt = 0; mt < 2; mt++)
#pragma unroll
            for (int nt = 0; nt < 4; nt++) {
                int m = m0 + mt * 16 + g;
                int e = e0w + nt * 8 + 2 * q;
                ht[e * 136 + m]           = __float2half(siluf(accN[mt][nt][0] + s_nb1[m]));
                ht[(e + 1) * 136 + m]     = __float2half(siluf(accN[mt][nt][1] + s_nb1[m]));
                ht[e * 136 + m + 8]       = __float2half(siluf(accN[mt][nt][2] + s_nb1[m + 8]));
                ht[(e + 1) * 136 + m + 8] = __float2half(siluf(accN[mt][nt][3] + s_nb1[m + 8]));
            }
    }
    __syncthreads();

    // node layer 2
    stage_wh(s_w, nW2, 128, tid, WTHREADS);
    __syncthreads();
    {
        float acc[2][4][4];
#pragma unroll
        for (int a = 0; a < 2; a++)
#pragma unroll
            for (int b = 0; b < 4; b++)
#pragma unroll
                for (int c = 0; c < 4; c++) acc[a][b][c] = 0.f;
        gemm_h<2, 4>(s_w, s_t, acc, m0, e0w, lane);
#pragma unroll
        for (int mt = 0; mt < 2; mt++)
#pragma unroll
            for (int nt = 0; nt < 4; nt++) {
                int m = m0 + mt * 16 + g;
                int e = e0w + nt * 8 + 2 * q;
#pragma unroll
                for (int c = 0; c < 4; c++) {
                    int mm = m + ((c >> 1) ? 8 : 0);
                    int ee = e + (c & 1);
                    int n = n0 + ee;
                    if (n < N)
                        out[(size_t)n * 128 + mm] = acc[mt][nt][c] + s_nb2[mm];
                }
            }
    }

    if (tid < 128) {
        int n = n0 + tid;
        if (n < N) {
            float vs = s_vel[tid];
            float v0 = vinit[(size_t)n * 3 + 0] * vs;
            float v1 = vinit[(size_t)n * 3 + 1] * vs;
            float v2 = vinit[(size_t)n * 3 + 2] * vs;
            float* out_x = out + (size_t)N * 128;
            float* out_v = out_x + (size_t)N * 3;
            out_v[(size_t)n * 3 + 0] = v0;
            out_v[(size_t)n * 3 + 1] = v1;
            out_v[(size_t)n * 3 + 2] = v2;
            float x0 = x[(size_t)n * 3 + 0], x1 = x[(size_t)n * 3 + 1], x2 = x[(size_t)n * 3 + 2];
            if (hase[n]) {
                x0 += v0 + aggx[(size_t)n * 3 + 0] * invNm1;
                x1 += v1 + aggx[(size_t)n * 3 + 1] * invNm1;
                x2 += v2 + aggx[(size_t)n * 3 + 2] * invNm1;
            }
            out_x[(size_t)n * 3 + 0] = x0;
            out_x[(size_t)n * 3 + 1] = x1;
            out_x[(size_t)n * 3 + 2] = x2;
        }
    }
}

// ============================================================================
// Launch
// ============================================================================
extern "C" void kernel_launch(void* const* d_in, const int* in_sizes, int n_in,
                              void* d_out, int out_size) {
    const float* h     = (const float*)d_in[0];
    const float* x     = (const float*)d_in[1];
    const float* eattr = (const float*)d_in[2];
    const float* vinit = (const float*)d_in[3];
    const int*   ei    = (const int*)d_in[4];
    const float* eW1 = (const float*)d_in[5];
    const float* eb1 = (const float*)d_in[6];
    const float* eW2 = (const float*)d_in[7];
    const float* eb2 = (const float*)d_in[8];
    const float* cW1 = (const float*)d_in[9];
    const float* cb1 = (const float*)d_in[10];
    const float* cW2 = (const float*)d_in[11];
    const float* iW1 = (const float*)d_in[12];
    const float* ib1 = (const float*)d_in[13];
    const float* iW2 = (const float*)d_in[14];
    const float* ib2 = (const float*)d_in[15];
    const float* nW1 = (const float*)d_in[16];
    const float* nb1 = (const float*)d_in[17];
    const float* nW2 = (const float*)d_in[18];
    const float* nb2 = (const float*)d_in[19];
    const float* vW1 = (const float*)d_in[20];
    const float* vb1 = (const float*)d_in[21];
    const float* vW2 = (const float*)d_in[22];

    const int N = in_sizes[0] / 128;
    const int E = in_sizes[2];
    float* out = (float*)d_out;
    const float invNm1 = 1.0f / (float)(N - 1);

    void *p_mi, *p_ax, *p_he, *p_P, *p_Q;
    cudaGetSymbolAddress(&p_mi, g_mi);
    cudaGetSymbolAddress(&p_ax, g_aggx);
    cudaGetSymbolAddress(&p_he, g_hase);
    cudaGetSymbolAddress(&p_P, g_P);
    cudaGetSymbolAddress(&p_Q, g_Q);
    cudaMemsetAsync(p_mi, 0, (size_t)N * 128 * sizeof(float));
    cudaMemsetAsync(p_ax, 0, (size_t)N * 3 * sizeof(float));
    cudaMemsetAsync(p_he, 0, (size_t)N * sizeof(int));

    cudaFuncSetAttribute(egnn_pq_kernel,
                         cudaFuncAttributeMaxDynamicSharedMemorySize, PQ_SMEM);
    cudaFuncSetAttribute(egnn_edge_persist,
                         cudaFuncAttributeMaxDynamicSharedMemorySize, E_SMEM);
    cudaFuncSetAttribute(egnn_node_kernel,
                         cudaFuncAttributeMaxDynamicSharedMemorySize, N_SMEM);

    int nblocks = (N + 127) / 128;
    egnn_pq_kernel<<<nblocks, PQTHREADS, PQ_SMEM>>>(h, eW1, (float*)p_P, (float*)p_Q, N);

    int ntiles = (E + ETILE - 1) / ETILE;
    egnn_edge_persist<<<EGRID, WTHREADS, E_SMEM>>>(
        x, eattr, ei, eW1, eb1, eW2, eb2, cW1, cb1, cW2,
        iW1, ib1, iW2, ib2,
        (const float*)p_P, (const float*)p_Q,
        (float*)p_mi, (float*)p_ax, (int*)p_he, E, ntiles);

    egnn_node_kernel<<<nblocks, WTHREADS, N_SMEM>>>(
        h, x, vinit, nW1, nb1, nW2, nb2, vW1, vb1, vW2,
        (const float*)p_mi, (const float*)p_ax, (const int*)p_he,
        out, N, invNm1);
}